// round 5
// baseline (speedup 1.0000x reference)
#include <cuda_runtime.h>
#include <math.h>
#include <stdint.h>

#define BB 128
#define SS 512
#define NN 32
#define DD 512
#define HH 2
#define MM (BB*NN)   // 4096 rows

#define KCH 32                 // K elements per pipeline chunk
#define APITCH 36              // smem row pitch in floats (conflict-free frags)
#define STG_FLTS (128*APITCH)  // 4608 floats per matrix per stage
#define STG2 (2*STG_FLTS)      // floats per stage (A+B)
#define NSTG 2
#define SMEM_DYN (NSTG*STG2*4)  // 73728 bytes -> 2 CTAs/SM

// ---------------- scratch (device globals; no allocation) ----------------
__device__ float g_gt_buf[BB*NN*NN];
__device__ float g_lt_buf[BB*NN*NN];
__device__ int   invmap_buf[BB*SS];
__device__ float buf_nodeA[MM*DD];
__device__ float buf_nodeB[MM*DD];
__device__ float buf_t1[MM*DD];
__device__ float buf_t2[MM*DD];
__device__ float buf_t3[MM*DD];
__device__ float buf_t4[MM*DD];
__device__ float buf_ni1[MM*DD];
__device__ float buf_ni2[MM*DD];
__device__ float buf_ninfo[MM*DD];
__device__ float buf_WT[16*DD*DD];   // transposed (tf32-rounded) weights [N,K]

// ---------------- helpers ----------------
__device__ __forceinline__ uint32_t smem_u32(const void* p) {
    return (uint32_t)__cvta_generic_to_shared(p);
}
__device__ __forceinline__ float to_tf32(float x) {
    uint32_t r; asm("cvt.rna.tf32.f32 %0, %1;" : "=r"(r) : "f"(x));
    return __uint_as_float(r);
}
__device__ __forceinline__ void cp_async16(uint32_t dst, const void* src) {
    asm volatile("cp.async.cg.shared.global [%0], [%1], 16;" :: "r"(dst), "l"(src));
}
__device__ __forceinline__ void mma_tf32(float* c, const uint32_t* a,
                                         uint32_t b0, uint32_t b1) {
    asm volatile("mma.sync.aligned.m16n8k8.row.col.f32.tf32.tf32.f32 "
                 "{%0,%1,%2,%3}, {%4,%5,%6,%7}, {%8,%9}, {%0,%1,%2,%3};"
                 : "+f"(c[0]), "+f"(c[1]), "+f"(c[2]), "+f"(c[3])
                 : "r"(a[0]), "r"(a[1]), "r"(a[2]), "r"(a[3]), "r"(b0), "r"(b1));
}

// ---------------- graph construction (+ invmap) ----------------
__global__ void build_graphs_inv(const int* __restrict__ order, const int* __restrict__ pos,
                                 float* __restrict__ g_gt, float* __restrict__ g_lt,
                                 int* __restrict__ invmap) {
    int b = blockIdx.x;
    __shared__ int ord[NN];
    int tid = threadIdx.x;              // 1024 threads = NN*NN
    if (tid < NN) ord[tid] = order[b*NN + tid];
    if (tid < SS) invmap[b*SS + tid] = -1;
    __syncthreads();
    if (tid < NN) {
        int p = pos[b*NN + tid];
        if (p >= 0) invmap[b*SS + p] = b*NN + tid;
    }
    int n = tid >> 5, m = tid & 31;
    int on = ord[n], om = ord[m];
    float pair = (on > 0 && om > 0 && n != m) ? 1.f : 0.f;
    float eye  = (n == m) ? 1.f : 0.f;
    float vg = pair * ((on > om) ? 1.f : 0.f) + eye;
    float vl = pair * ((on > om) ? 0.f : 1.f) + eye;
    float sg = vg, sl = vl;
    #pragma unroll
    for (int off = 16; off; off >>= 1) {
        sg += __shfl_xor_sync(0xffffffffu, sg, off);
        sl += __shfl_xor_sync(0xffffffffu, sl, off);
    }
    g_gt[b*NN*NN + tid] = vg / sg;
    g_lt[b*NN*NN + tid] = vl / sl;
}

// ---------------- dual graph aggregation (z=0: gt/x0->y0, z=1: lt/x1->y1) ------
__global__ void graph_agg2(const float* __restrict__ g_gt, const float* __restrict__ g_lt,
                           const float* __restrict__ x0, const float* __restrict__ x1,
                           float* __restrict__ y0, float* __restrict__ y1) {
    int b = blockIdx.x;
    const float* g = blockIdx.z ? g_lt : g_gt;
    const float* x = blockIdx.z ? x1 : x0;
    float* y       = blockIdx.z ? y1 : y0;
    int d = blockIdx.y * 128 + threadIdx.x;    // 128 threads
    __shared__ float gs[NN*NN];
    for (int i = threadIdx.x; i < NN*NN; i += 128) gs[i] = g[b*NN*NN + i];
    __syncthreads();
    const float* xb = x + (size_t)b*NN*DD + d;
    float xv[NN];
    #pragma unroll
    for (int m = 0; m < NN; m++) xv[m] = xb[(size_t)m*DD];
    float* yb = y + (size_t)b*NN*DD + d;
    #pragma unroll
    for (int n = 0; n < NN; n++) {
        float acc = 0.f;
        #pragma unroll
        for (int m = 0; m < NN; m++) acc = fmaf(gs[n*NN+m], xv[m], acc);
        yb[(size_t)n*DD] = acc;
    }
}

// ---------------- single-launch weight transpose ([K,N]->[N,K], tf32-rounded) ---
struct TJob { const float* src; float* d1; float* d2; int gate; };
struct TArgs { TJob j[14]; };

__global__ void transpose_all(TArgs A) {
    TJob job = A.j[blockIdx.z];
    __shared__ float t1s[32][33], t2s[32][33];
    int k0 = blockIdx.x*32, n0 = blockIdx.y*32;
    int tx = threadIdx.x, ty = threadIdx.y;
    if (!job.gate) {
        #pragma unroll
        for (int i = 0; i < 4; i++)
            t1s[ty + i*8][tx] = job.src[(size_t)(k0 + ty + i*8)*DD + n0 + tx];
        __syncthreads();
        #pragma unroll
        for (int i = 0; i < 4; i++)
            job.d1[(size_t)(n0 + ty + i*8)*DD + k0 + tx] = to_tf32(t1s[tx][ty + i*8]);
    } else {
        #pragma unroll
        for (int i = 0; i < 4; i++) {
            int k = k0 + ty + i*8, n = n0 + tx;
            float w0 = job.src[(size_t)k*DD + n];
            float w1 = job.src[(size_t)(DD + k)*DD + n];
            float w2 = job.src[(size_t)(2*DD + k)*DD + n];
            float w3 = job.src[(size_t)(3*DD + k)*DD + n];
            t1s[ty + i*8][tx] = w0 + w2 + w3;
            t2s[ty + i*8][tx] = w1 + w2 - w3;
        }
        __syncthreads();
        #pragma unroll
        for (int i = 0; i < 4; i++) {
            size_t o = (size_t)(n0 + ty + i*8)*DD + k0 + tx;
            job.d1[o] = to_tf32(t1s[tx][ty + i*8]);
            job.d2[o] = to_tf32(t2s[tx][ty + i*8]);
        }
    }
}

// ---------------- TF32 mma.sync GEMM ----------------
struct GemmPair {
    const float *A1[2], *W1[2], *A2[2], *W2[2], *bias[2];
    const float *e1, *e2;
    float *out[2];
    int nK;
};

__device__ __forceinline__ void load_chunk(float* smbase, const float* Asrc,
                                           const float* Wsrc, int bm, int bn,
                                           int kk, int tid) {
    float* Asm = smbase;
    float* Bsm = smbase + STG_FLTS;
    #pragma unroll
    for (int j = 0; j < 4; j++) {
        int f = tid + 256*j; int row = f >> 3, c4 = f & 7;
        cp_async16(smem_u32(Asm + row*APITCH + c4*4),
                   Asrc + (size_t)(bm + row)*512 + kk + c4*4);
    }
    #pragma unroll
    for (int j = 0; j < 4; j++) {
        int f = tid + 256*j; int row = f >> 3, c4 = f & 7;
        cp_async16(smem_u32(Bsm + row*APITCH + c4*4),
                   Wsrc + (size_t)(bn + row)*512 + kk + c4*4);
    }
}

#define FRAG_LOAD(buf, k8) do {                                              \
    int kb_ = (k8)*8 + (lane & 3);                                           \
    _Pragma("unroll")                                                        \
    for (int mi_ = 0; mi_ < 2; mi_++) {                                      \
        const float* ap_ = Abase + (mi_*16 + (lane >> 2))*APITCH + kb_;      \
        aR[buf][mi_][0] = __float_as_uint(ap_[0]);                           \
        aR[buf][mi_][1] = __float_as_uint(ap_[8*APITCH]);                    \
        aR[buf][mi_][2] = __float_as_uint(ap_[4]);                           \
        aR[buf][mi_][3] = __float_as_uint(ap_[8*APITCH + 4]);                \
    }                                                                        \
    _Pragma("unroll")                                                        \
    for (int ni_ = 0; ni_ < 8; ni_++) {                                      \
        const float* bp_ = Bbase + (ni_*8 + (lane >> 2))*APITCH + kb_;       \
        bR[buf][ni_][0] = __float_as_uint(bp_[0]);                           \
        bR[buf][ni_][1] = __float_as_uint(bp_[4]);                           \
    }                                                                        \
} while (0)

template<int EPI>
__global__ void __launch_bounds__(256, 2)
gemm_mma(GemmPair P)
{
    const int z = blockIdx.z;
    const float* A1 = P.A1[z]; const float* W1 = P.W1[z];
    const float* A2 = P.A2[z]; const float* W2 = P.W2[z];
    const float* bias = P.bias[z];
    float* out = P.out[z];
    const int nK = P.nK;

    extern __shared__ float sm[];
    const int bm = blockIdx.y * 128, bn = blockIdx.x * 128;
    const int tid = threadIdx.x, wid = tid >> 5, lane = tid & 31;
    const int wm = (wid >> 1) * 32, wn = (wid & 1) * 64;

    float acc[2][8][4];
    #pragma unroll
    for (int i = 0; i < 2; i++)
        #pragma unroll
        for (int j = 0; j < 8; j++)
            #pragma unroll
            for (int q = 0; q < 4; q++) acc[i][j][q] = 0.f;

    const int nc = nK / KCH;

    // prologue: chunk 0 -> stage 0
    load_chunk(sm, A1, W1, bm, bn, 0, tid);
    asm volatile("cp.async.commit_group;");

    for (int kc = 0; kc < nc; kc++) {
        int s = kc & 1;
        if (kc + 1 < nc) {
            int k = (kc + 1) * KCH;
            const float* As = (k < 512) ? A1 : A2;
            const float* Ws = (k < 512) ? W1 : W2;
            load_chunk(sm + (s^1)*STG2, As, Ws, bm, bn, k & 511, tid);
            asm volatile("cp.async.commit_group;");
            asm volatile("cp.async.wait_group 1;");
        } else {
            asm volatile("cp.async.wait_group 0;");
        }
        __syncthreads();

        const float* Abase = sm + s*STG2 + wm*APITCH;
        const float* Bbase = sm + s*STG2 + STG_FLTS + wn*APITCH;

        uint32_t aR[2][2][4];
        uint32_t bR[2][8][2];
        FRAG_LOAD(0, 0);
        #pragma unroll
        for (int k8 = 0; k8 < 4; k8++) {
            int cur = k8 & 1;
            if (k8 < 3) {
                int nxt = (k8 + 1) & 1;
                FRAG_LOAD(nxt, k8 + 1);
            }
            #pragma unroll
            for (int ni = 0; ni < 8; ni++) {
                mma_tf32(acc[0][ni], aR[cur][0], bR[cur][ni][0], bR[cur][ni][1]);
                mma_tf32(acc[1][ni], aR[cur][1], bR[cur][ni][0], bR[cur][ni][1]);
            }
        }
        __syncthreads();   // protect stage s before next overwrite (2-stage WAR)
    }

    // epilogue
    const int r0 = bm + wm + (lane >> 2);
    const int cbase = bn + wn + (lane & 3)*2;
    float bb0[8], bb1[8];
    #pragma unroll
    for (int ni = 0; ni < 8; ni++) {
        bb0[ni] = bias[cbase + ni*8];
        bb1[ni] = bias[cbase + ni*8 + 1];
    }
    #pragma unroll
    for (int mi = 0; mi < 2; mi++) {
        int row0 = r0 + mi*16, row1 = row0 + 8;
        #pragma unroll
        for (int ni = 0; ni < 8; ni++) {
            int col = cbase + ni*8;
            float v0 = acc[mi][ni][0] + bb0[ni];
            float v1 = acc[mi][ni][1] + bb1[ni];
            float v2 = acc[mi][ni][2] + bb0[ni];
            float v3 = acc[mi][ni][3] + bb1[ni];
            if (EPI == 1) {
                v0 = fmaxf(v0, 0.f); v1 = fmaxf(v1, 0.f);
                v2 = fmaxf(v2, 0.f); v3 = fmaxf(v3, 0.f);
            } else {
                float2 ea0 = *(const float2*)(P.e1 + (size_t)row0*512 + col);
                float2 eb0 = *(const float2*)(P.e2 + (size_t)row0*512 + col);
                float2 ea1 = *(const float2*)(P.e1 + (size_t)row1*512 + col);
                float2 eb1 = *(const float2*)(P.e2 + (size_t)row1*512 + col);
                float g0 = 1.f / (1.f + expf(-v0));
                float g1 = 1.f / (1.f + expf(-v1));
                float g2 = 1.f / (1.f + expf(-v2));
                float g3 = 1.f / (1.f + expf(-v3));
                v0 = g0*ea0.x + (1.f - g0)*eb0.x;
                v1 = g1*ea0.y + (1.f - g1)*eb0.y;
                v2 = g2*ea1.x + (1.f - g2)*eb1.x;
                v3 = g3*ea1.y + (1.f - g3)*eb1.y;
            }
            *(float2*)(out + (size_t)row0*512 + col) = make_float2(v0, v1);
            *(float2*)(out + (size_t)row1*512 + col) = make_float2(v2, v3);
        }
    }
}

// ---------------- output assembly ----------------
__global__ void add_f4(const float4* __restrict__ a, const float4* __restrict__ b,
                       float4* __restrict__ dst, int n4) {
    int i = blockIdx.x*blockDim.x + threadIdx.x;
    int stride = gridDim.x*blockDim.x;
    for (; i < n4; i += stride) {
        float4 x = a[i], y = b[i];
        dst[i] = make_float4(x.x+y.x, x.y+y.y, x.z+y.z, x.w+y.w);
    }
}

// gnn[s,b,:] = enc[s,b,:] + scattered node; po[b,:] = max_s gnn[s,b,:]
__global__ void fused_assemble(const float* __restrict__ enc, const float* __restrict__ node,
                               const int* __restrict__ invmap,
                               float* __restrict__ gnn, float* __restrict__ po) {
    int b = blockIdx.x;
    int d = blockIdx.y * 128 + threadIdx.x;
    __shared__ int inv[SS];
    for (int i = threadIdx.x; i < SS; i += 128) inv[i] = invmap[b*SS + i];
    __syncthreads();
    size_t base = (size_t)b*DD + d;
    float m = -3.402823466e38f;
    #pragma unroll 1
    for (int s = 0; s < SS; s += 4) {
        float v[4];
        #pragma unroll
        for (int u = 0; u < 4; u++)
            v[u] = enc[(size_t)(s + u)*BB*DD + base];
        #pragma unroll
        for (int u = 0; u < 4; u++) {
            int iv = inv[s + u];
            if (iv >= 0) v[u] += node[(size_t)iv*DD + d];
        }
        #pragma unroll
        for (int u = 0; u < 4; u++) {
            gnn[(size_t)(s + u)*BB*DD + base] = v[u];
            m = fmaxf(m, v[u]);
        }
    }
    po[base] = m;
}

// ---------------- host launch ----------------
extern "C" void kernel_launch(void* const* d_in, const int* in_sizes, int n_in,
                              void* d_out, int out_size) {
    const float* enc    = (const float*)d_in[0];   // [S,B,D]
    const float* numenc = (const float*)d_in[1];   // [B,N,D]
    const int*   pos    = (const int*)d_in[2];     // [B,N]
    const int*   order  = (const int*)d_in[3];     // [B,N]
    const float* w_n1a  = (const float*)d_in[4];
    const float* b_n1a  = (const float*)d_in[5];
    const float* w_n1b  = (const float*)d_in[6];
    const float* b_n1b  = (const float*)d_in[7];
    const float* w_n2a  = (const float*)d_in[8];
    const float* b_n2a  = (const float*)d_in[9];
    const float* w_n2b  = (const float*)d_in[10];
    const float* b_n2b  = (const float*)d_in[11];
    const float* w_g    = (const float*)d_in[12];  // [H,4D,D]
    const float* b_g    = (const float*)d_in[13];
    const float* w_o    = (const float*)d_in[14];  // [H,2D,D]
    const float* b_o    = (const float*)d_in[15];

    float* out     = (float*)d_out;
    float* out_gnn = out;                                    // [S,B,D]
    float* out_ne  = out + (size_t)SS*BB*DD;                 // [B,N,D]
    float* out_po  = out_ne + (size_t)BB*NN*DD;              // [B,D]

    float *g_gt, *g_lt, *nodeA, *nodeB, *t1, *t2, *t3, *t4, *ni1, *ni2, *ninfo, *WT;
    int* invmap;
    cudaGetSymbolAddress((void**)&g_gt,   g_gt_buf);
    cudaGetSymbolAddress((void**)&g_lt,   g_lt_buf);
    cudaGetSymbolAddress((void**)&invmap, invmap_buf);
    cudaGetSymbolAddress((void**)&nodeA,  buf_nodeA);
    cudaGetSymbolAddress((void**)&nodeB,  buf_nodeB);
    cudaGetSymbolAddress((void**)&t1,     buf_t1);
    cudaGetSymbolAddress((void**)&t2,     buf_t2);
    cudaGetSymbolAddress((void**)&t3,     buf_t3);
    cudaGetSymbolAddress((void**)&t4,     buf_t4);
    cudaGetSymbolAddress((void**)&ni1,    buf_ni1);
    cudaGetSymbolAddress((void**)&ni2,    buf_ni2);
    cudaGetSymbolAddress((void**)&ninfo,  buf_ninfo);
    cudaGetSymbolAddress((void**)&WT,     buf_WT);

    cudaFuncSetAttribute(gemm_mma<1>, cudaFuncAttributeMaxDynamicSharedMemorySize, SMEM_DYN);
    cudaFuncSetAttribute(gemm_mma<2>, cudaFuncAttributeMaxDynamicSharedMemorySize, SMEM_DYN);

    build_graphs_inv<<<BB, NN*NN>>>(order, pos, g_gt, g_lt, invmap);

    // all weight transposes in one launch
    {
        TArgs TA;
        for (int h = 0; h < HH; h++) {
            float* base = WT + (size_t)h*8*DD*DD;
            TJob* j = TA.j + h*7;
            j[0] = { w_n1a + (size_t)h*DD*DD, base + 0*(size_t)DD*DD, nullptr, 0 };
            j[1] = { w_n1b + (size_t)h*DD*DD, base + 1*(size_t)DD*DD, nullptr, 0 };
            j[2] = { w_n2a + (size_t)h*DD*DD, base + 2*(size_t)DD*DD, nullptr, 0 };
            j[3] = { w_n2b + (size_t)h*DD*DD, base + 3*(size_t)DD*DD, nullptr, 0 };
            j[4] = { w_o + (size_t)h*2*DD*DD,                  base + 6*(size_t)DD*DD, nullptr, 0 };
            j[5] = { w_o + (size_t)h*2*DD*DD + (size_t)DD*DD,  base + 7*(size_t)DD*DD, nullptr, 0 };
            j[6] = { w_g + (size_t)h*4*DD*DD, base + 4*(size_t)DD*DD, base + 5*(size_t)DD*DD, 1 };
        }
        transpose_all<<<dim3(16,16,14), dim3(32,8)>>>(TA);
    }

    const float* node = numenc;          // hop-0 input read directly
    float* nodeOut[2] = { nodeA, nodeB };
    for (int h = 0; h < HH; h++) {
        float* base = WT + (size_t)h*8*DD*DD;

        // u1 = g_gt @ node, u2 = g_lt @ node
        graph_agg2<<<dim3(BB,4,2), 128>>>(g_gt, g_lt, node, node, t1, t2);

        // v1 = relu(u1@w1a + b), v2 = relu(u2@w2a + b)
        {
            GemmPair P = {};
            P.A1[0]=t1; P.W1[0]=base+0*(size_t)DD*DD; P.bias[0]=b_n1a+h*DD; P.out[0]=t3;
            P.A1[1]=t2; P.W1[1]=base+2*(size_t)DD*DD; P.bias[1]=b_n2a+h*DD; P.out[1]=t4;
            P.nK = 512;
            gemm_mma<1><<<dim3(4,32,2), 256, SMEM_DYN>>>(P);
        }

        // u1b = g_gt @ v1, u2b = g_lt @ v2
        graph_agg2<<<dim3(BB,4,2), 128>>>(g_gt, g_lt, t3, t4, t1, t2);

        // ni1 = relu(u1b@w1b + b), ni2 = relu(u2b@w2b + b)
        {
            GemmPair P = {};
            P.A1[0]=t1; P.W1[0]=base+1*(size_t)DD*DD; P.bias[0]=b_n1b+h*DD; P.out[0]=ni1;
            P.A1[1]=t2; P.W1[1]=base+3*(size_t)DD*DD; P.bias[1]=b_n2b+h*DD; P.out[1]=ni2;
            P.nK = 512;
            gemm_mma<1><<<dim3(4,32,2), 256, SMEM_DYN>>>(P);
        }

        // ninfo = sig(ni1@Wg1 + ni2@Wg2 + b_g)*ni1 + (1-.)*ni2
        {
            GemmPair P = {};
            P.A1[0]=ni1; P.W1[0]=base+4*(size_t)DD*DD;
            P.A2[0]=ni2; P.W2[0]=base+5*(size_t)DD*DD;
            P.bias[0]=b_g+h*DD; P.out[0]=ninfo;
            P.e1=ni1; P.e2=ni2; P.nK = 1024;
            gemm_mma<2><<<dim3(4,32,1), 256, SMEM_DYN>>>(P);
        }

        // node' = relu(node@woA + ninfo@woB + b_o)
        {
            GemmPair P = {};
            P.A1[0]=node;  P.W1[0]=base+6*(size_t)DD*DD;
            P.A2[0]=ninfo; P.W2[0]=base+7*(size_t)DD*DD;
            P.bias[0]=b_o+h*DD; P.out[0]=nodeOut[h]; P.nK = 1024;
            gemm_mma<1><<<dim3(4,32,1), 256, SMEM_DYN>>>(P);
        }
        node = nodeOut[h];
    }

    fused_assemble<<<dim3(BB,4), 128>>>(enc, node, invmap, out_gnn, out_po);
    add_f4<<<2048, 256>>>((const float4*)numenc, (const float4*)node,
                          (float4*)out_ne, MM*DD/4);
}

// round 6
// speedup vs baseline: 1.0763x; 1.0763x over previous
#include <cuda_runtime.h>
#include <math.h>
#include <stdint.h>

#define BB 128
#define SS 512
#define NN 32
#define DD 512
#define HH 2
#define MM (BB*NN)   // 4096 rows

#define KCH 32                 // K elements per pipeline chunk
#define APITCH 36              // smem row pitch in floats (conflict-free frags/ldsm)
#define STG_FLTS (128*APITCH)  // 4608 floats per matrix per stage
#define STG2 (2*STG_FLTS)      // floats per stage (A+B)
#define NSTG 3
#define SMEM_DYN (NSTG*STG2*4)  // 110592 bytes -> 2 CTAs/SM
#define NC 16                   // K chunks (K=512 always)

// ---------------- scratch (device globals; no allocation) ----------------
__device__ float g_gt_buf[BB*NN*NN];
__device__ float g_lt_buf[BB*NN*NN];
__device__ int   invmap_buf[BB*SS];
__device__ float buf_nodeA[MM*DD];
__device__ float buf_nodeB[MM*DD];
__device__ float buf_t1[MM*DD];
__device__ float buf_t2[MM*DD];
__device__ float buf_t3[MM*DD];
__device__ float buf_t4[MM*DD];
__device__ float buf_ni1[MM*DD];
__device__ float buf_ni2[MM*DD];
__device__ float buf_ninfo[MM*DD];
__device__ float buf_WT[16*DD*DD];   // transposed (tf32-rounded) weights [N,K]

// ---------------- helpers ----------------
__device__ __forceinline__ uint32_t smem_u32(const void* p) {
    return (uint32_t)__cvta_generic_to_shared(p);
}
__device__ __forceinline__ float to_tf32(float x) {
    uint32_t r; asm("cvt.rna.tf32.f32 %0, %1;" : "=r"(r) : "f"(x));
    return __uint_as_float(r);
}
__device__ __forceinline__ void cp_async16(uint32_t dst, const void* src) {
    asm volatile("cp.async.cg.shared.global [%0], [%1], 16;" :: "r"(dst), "l"(src));
}
__device__ __forceinline__ void mma_tf32(float* c, const uint32_t* a,
                                         uint32_t b0, uint32_t b1) {
    asm volatile("mma.sync.aligned.m16n8k8.row.col.f32.tf32.tf32.f32 "
                 "{%0,%1,%2,%3}, {%4,%5,%6,%7}, {%8,%9}, {%0,%1,%2,%3};"
                 : "+f"(c[0]), "+f"(c[1]), "+f"(c[2]), "+f"(c[3])
                 : "r"(a[0]), "r"(a[1]), "r"(a[2]), "r"(a[3]), "r"(b0), "r"(b1));
}
__device__ __forceinline__ void ldsm_x4(uint32_t addr, uint32_t* r) {
    asm volatile("ldmatrix.sync.aligned.m8n8.x4.shared.b16 {%0,%1,%2,%3}, [%4];"
                 : "=r"(r[0]), "=r"(r[1]), "=r"(r[2]), "=r"(r[3]) : "r"(addr));
}

// ---------------- graph construction (+ invmap) ----------------
__global__ void build_graphs_inv(const int* __restrict__ order, const int* __restrict__ pos,
                                 float* __restrict__ g_gt, float* __restrict__ g_lt,
                                 int* __restrict__ invmap) {
    int b = blockIdx.x;
    __shared__ int ord[NN];
    int tid = threadIdx.x;              // 1024 threads = NN*NN
    if (tid < NN) ord[tid] = order[b*NN + tid];
    if (tid < SS) invmap[b*SS + tid] = -1;
    __syncthreads();
    if (tid < NN) {
        int p = pos[b*NN + tid];
        if (p >= 0) invmap[b*SS + p] = b*NN + tid;
    }
    int n = tid >> 5, m = tid & 31;
    int on = ord[n], om = ord[m];
    float pair = (on > 0 && om > 0 && n != m) ? 1.f : 0.f;
    float eye  = (n == m) ? 1.f : 0.f;
    float vg = pair * ((on > om) ? 1.f : 0.f) + eye;
    float vl = pair * ((on > om) ? 0.f : 1.f) + eye;
    float sg = vg, sl = vl;
    #pragma unroll
    for (int off = 16; off; off >>= 1) {
        sg += __shfl_xor_sync(0xffffffffu, sg, off);
        sl += __shfl_xor_sync(0xffffffffu, sl, off);
    }
    g_gt[b*NN*NN + tid] = vg / sg;
    g_lt[b*NN*NN + tid] = vl / sl;
}

// ---------------- dual graph aggregation (z=0: gt/x0->y0, z=1: lt/x1->y1) ------
__global__ void graph_agg2(const float* __restrict__ g_gt, const float* __restrict__ g_lt,
                           const float* __restrict__ x0, const float* __restrict__ x1,
                           float* __restrict__ y0, float* __restrict__ y1) {
    int b = blockIdx.x;
    const float* g = blockIdx.z ? g_lt : g_gt;
    const float* x = blockIdx.z ? x1 : x0;
    float* y       = blockIdx.z ? y1 : y0;
    int d = blockIdx.y * 128 + threadIdx.x;    // 128 threads
    __shared__ float gs[NN*NN];
    for (int i = threadIdx.x; i < NN*NN; i += 128) gs[i] = g[b*NN*NN + i];
    __syncthreads();
    const float* xb = x + (size_t)b*NN*DD + d;
    float xv[NN];
    #pragma unroll
    for (int m = 0; m < NN; m++) xv[m] = xb[(size_t)m*DD];
    float* yb = y + (size_t)b*NN*DD + d;
    #pragma unroll
    for (int n = 0; n < NN; n++) {
        float acc = 0.f;
        #pragma unroll
        for (int m = 0; m < NN; m++) acc = fmaf(gs[n*NN+m], xv[m], acc);
        yb[(size_t)n*DD] = acc;
    }
}

// ---------------- single-launch weight transpose ([K,N]->[N,K], tf32-rounded) ---
struct TJob { const float* src; float* d1; float* d2; int gate; };
struct TArgs { TJob j[14]; };

__global__ void transpose_all(TArgs A) {
    TJob job = A.j[blockIdx.z];
    __shared__ float t1s[32][33], t2s[32][33];
    int k0 = blockIdx.x*32, n0 = blockIdx.y*32;
    int tx = threadIdx.x, ty = threadIdx.y;
    if (!job.gate) {
        #pragma unroll
        for (int i = 0; i < 4; i++)
            t1s[ty + i*8][tx] = job.src[(size_t)(k0 + ty + i*8)*DD + n0 + tx];
        __syncthreads();
        #pragma unroll
        for (int i = 0; i < 4; i++)
            job.d1[(size_t)(n0 + ty + i*8)*DD + k0 + tx] = to_tf32(t1s[tx][ty + i*8]);
    } else {
        #pragma unroll
        for (int i = 0; i < 4; i++) {
            int k = k0 + ty + i*8, n = n0 + tx;
            float w0 = job.src[(size_t)k*DD + n];
            float w1 = job.src[(size_t)(DD + k)*DD + n];
            float w2 = job.src[(size_t)(2*DD + k)*DD + n];
            float w3 = job.src[(size_t)(3*DD + k)*DD + n];
            t1s[ty + i*8][tx] = w0 + w2 + w3;
            t2s[ty + i*8][tx] = w1 + w2 - w3;
        }
        __syncthreads();
        #pragma unroll
        for (int i = 0; i < 4; i++) {
            size_t o = (size_t)(n0 + ty + i*8)*DD + k0 + tx;
            job.d1[o] = to_tf32(t1s[tx][ty + i*8]);
            job.d2[o] = to_tf32(t2s[tx][ty + i*8]);
        }
    }
}

// ---------------- TF32 mma.sync GEMM (K=512 fixed, ldmatrix frags) --------------
// out_z = epi(A_z @ W_z^T [+ bias_z]);  EPI 0: raw (no bias), EPI 1: bias+relu
struct GemmPair {
    const float *A[2], *W[2], *bias[2];
    float *out[2];
};

__device__ __forceinline__ void load_chunk(float* smbase, const float* Asrc,
                                           const float* Wsrc, int bm, int bn,
                                           int kk, int tid) {
    float* Asm = smbase;
    float* Bsm = smbase + STG_FLTS;
    #pragma unroll
    for (int j = 0; j < 4; j++) {
        int f = tid + 256*j; int row = f >> 3, c4 = f & 7;
        cp_async16(smem_u32(Asm + row*APITCH + c4*4),
                   Asrc + (size_t)(bm + row)*512 + kk + c4*4);
    }
    #pragma unroll
    for (int j = 0; j < 4; j++) {
        int f = tid + 256*j; int row = f >> 3, c4 = f & 7;
        cp_async16(smem_u32(Bsm + row*APITCH + c4*4),
                   Wsrc + (size_t)(bn + row)*512 + kk + c4*4);
    }
}

template<int EPI>
__global__ void __launch_bounds__(256, 2)
gemm_mma(GemmPair P)
{
    const int z = blockIdx.z;
    const float* A = P.A[z]; const float* W = P.W[z];
    const float* bias = P.bias[z];
    float* out = P.out[z];

    extern __shared__ float sm[];
    const int bm = blockIdx.y * 128, bn = blockIdx.x * 128;
    const int tid = threadIdx.x, wid = tid >> 5, lane = tid & 31;
    const int wm = (wid >> 1) * 32, wn = (wid & 1) * 64;

    // per-lane ldmatrix row addresses
    const int laneAr = (lane & 7) + ((lane & 8) ? 8 : 0);
    const int laneAc = (lane & 16) ? 4 : 0;
    const int laneBr = (lane & 7) + ((lane & 16) ? 8 : 0);
    const int laneBc = (lane & 8) ? 4 : 0;
    const uint32_t smb = smem_u32(sm);
    uint32_t aAddr[2], bAddr[4];
    #pragma unroll
    for (int mi = 0; mi < 2; mi++)
        aAddr[mi] = smb + ((wm + mi*16 + laneAr)*APITCH + laneAc)*4;
    #pragma unroll
    for (int p = 0; p < 4; p++)
        bAddr[p] = smb + (STG_FLTS + (wn + p*16 + laneBr)*APITCH + laneBc)*4;

    float acc[2][8][4];
    #pragma unroll
    for (int i = 0; i < 2; i++)
        #pragma unroll
        for (int j = 0; j < 8; j++)
            #pragma unroll
            for (int q = 0; q < 4; q++) acc[i][j][q] = 0.f;

    // prologue: chunks 0,1 -> stages 0,1
    load_chunk(sm, A, W, bm, bn, 0, tid);
    asm volatile("cp.async.commit_group;");
    load_chunk(sm + STG2, A, W, bm, bn, KCH, tid);
    asm volatile("cp.async.commit_group;");

    int rs = 0, ws = 2;
    #pragma unroll 1
    for (int kc = 0; kc < NC; kc++) {
        if (kc + 1 < NC) asm volatile("cp.async.wait_group 1;");
        else             asm volatile("cp.async.wait_group 0;");
        __syncthreads();

        if (kc + 2 < NC) {
            load_chunk(sm + ws*STG2, A, W, bm, bn, (kc + 2)*KCH, tid);
            asm volatile("cp.async.commit_group;");
        }

        const uint32_t soff = (uint32_t)rs * (STG2*4);
        #pragma unroll
        for (int k8 = 0; k8 < 4; k8++) {
            const uint32_t koff = soff + k8*32;
            uint32_t aF[2][4], bF[4][4];
            ldsm_x4(aAddr[0] + koff, aF[0]);
            ldsm_x4(aAddr[1] + koff, aF[1]);
            #pragma unroll
            for (int p = 0; p < 4; p++) ldsm_x4(bAddr[p] + koff, bF[p]);
            #pragma unroll
            for (int p = 0; p < 4; p++) {
                mma_tf32(acc[0][2*p],   aF[0], bF[p][0], bF[p][1]);
                mma_tf32(acc[1][2*p],   aF[1], bF[p][0], bF[p][1]);
                mma_tf32(acc[0][2*p+1], aF[0], bF[p][2], bF[p][3]);
                mma_tf32(acc[1][2*p+1], aF[1], bF[p][2], bF[p][3]);
            }
        }
        rs = (rs + 1 == NSTG) ? 0 : rs + 1;
        ws = (ws + 1 == NSTG) ? 0 : ws + 1;
    }

    // epilogue
    const int r0 = bm + wm + (lane >> 2);
    const int cbase = bn + wn + (lane & 3)*2;
    float bb0[8], bb1[8];
    if (EPI == 1) {
        #pragma unroll
        for (int ni = 0; ni < 8; ni++) {
            bb0[ni] = bias[cbase + ni*8];
            bb1[ni] = bias[cbase + ni*8 + 1];
        }
    }
    #pragma unroll
    for (int mi = 0; mi < 2; mi++) {
        int row0 = r0 + mi*16, row1 = row0 + 8;
        #pragma unroll
        for (int ni = 0; ni < 8; ni++) {
            int col = cbase + ni*8;
            float v0 = acc[mi][ni][0], v1 = acc[mi][ni][1];
            float v2 = acc[mi][ni][2], v3 = acc[mi][ni][3];
            if (EPI == 1) {
                v0 = fmaxf(v0 + bb0[ni], 0.f); v1 = fmaxf(v1 + bb1[ni], 0.f);
                v2 = fmaxf(v2 + bb0[ni], 0.f); v3 = fmaxf(v3 + bb1[ni], 0.f);
            }
            *(float2*)(out + (size_t)row0*512 + col) = make_float2(v0, v1);
            *(float2*)(out + (size_t)row1*512 + col) = make_float2(v2, v3);
        }
    }
}

// ---------------- split-K combine kernels ----------------
// gate: out = sig(p0+p1+bias)*e1 + (1-sig)*e2
__global__ void combine_gate(const float4* __restrict__ p0, const float4* __restrict__ p1,
                             const float4* __restrict__ bias,
                             const float4* __restrict__ e1, const float4* __restrict__ e2,
                             float4* __restrict__ out) {
    int i = blockIdx.x*256 + threadIdx.x;       // MM*DD/4 threads
    float4 a = p0[i], b = p1[i], bi = bias[i & 127];
    float4 x = e1[i], y = e2[i];
    float g0 = 1.f/(1.f + expf(-(a.x + b.x + bi.x)));
    float g1 = 1.f/(1.f + expf(-(a.y + b.y + bi.y)));
    float g2 = 1.f/(1.f + expf(-(a.z + b.z + bi.z)));
    float g3 = 1.f/(1.f + expf(-(a.w + b.w + bi.w)));
    out[i] = make_float4(g0*x.x + (1.f-g0)*y.x, g1*x.y + (1.f-g1)*y.y,
                         g2*x.z + (1.f-g2)*y.z, g3*x.w + (1.f-g3)*y.w);
}

// relu: out = relu(p0+p1+bias); optionally out2 = addsrc + out
__global__ void combine_relu(const float4* __restrict__ p0, const float4* __restrict__ p1,
                             const float4* __restrict__ bias, float4* __restrict__ out,
                             const float4* __restrict__ addsrc, float4* __restrict__ out2) {
    int i = blockIdx.x*256 + threadIdx.x;
    float4 a = p0[i], b = p1[i], bi = bias[i & 127];
    float4 v = make_float4(fmaxf(a.x + b.x + bi.x, 0.f), fmaxf(a.y + b.y + bi.y, 0.f),
                           fmaxf(a.z + b.z + bi.z, 0.f), fmaxf(a.w + b.w + bi.w, 0.f));
    out[i] = v;
    if (addsrc) {
        float4 s = addsrc[i];
        out2[i] = make_float4(s.x + v.x, s.y + v.y, s.z + v.z, s.w + v.w);
    }
}

// gnn[s,b,:] = enc[s,b,:] + scattered node; po[b,:] = max_s gnn[s,b,:]
__global__ void fused_assemble(const float* __restrict__ enc, const float* __restrict__ node,
                               const int* __restrict__ invmap,
                               float* __restrict__ gnn, float* __restrict__ po) {
    int b = blockIdx.x;
    int d = blockIdx.y * 128 + threadIdx.x;
    __shared__ int inv[SS];
    for (int i = threadIdx.x; i < SS; i += 128) inv[i] = invmap[b*SS + i];
    __syncthreads();
    size_t base = (size_t)b*DD + d;
    float m = -3.402823466e38f;
    #pragma unroll 1
    for (int s = 0; s < SS; s += 4) {
        float v[4];
        #pragma unroll
        for (int u = 0; u < 4; u++)
            v[u] = enc[(size_t)(s + u)*BB*DD + base];
        #pragma unroll
        for (int u = 0; u < 4; u++) {
            int iv = inv[s + u];
            if (iv >= 0) v[u] += node[(size_t)iv*DD + d];
        }
        #pragma unroll
        for (int u = 0; u < 4; u++) {
            gnn[(size_t)(s + u)*BB*DD + base] = v[u];
            m = fmaxf(m, v[u]);
        }
    }
    po[base] = m;
}

// ---------------- host launch ----------------
extern "C" void kernel_launch(void* const* d_in, const int* in_sizes, int n_in,
                              void* d_out, int out_size) {
    const float* enc    = (const float*)d_in[0];   // [S,B,D]
    const float* numenc = (const float*)d_in[1];   // [B,N,D]
    const int*   pos    = (const int*)d_in[2];     // [B,N]
    const int*   order  = (const int*)d_in[3];     // [B,N]
    const float* w_n1a  = (const float*)d_in[4];
    const float* b_n1a  = (const float*)d_in[5];
    const float* w_n1b  = (const float*)d_in[6];
    const float* b_n1b  = (const float*)d_in[7];
    const float* w_n2a  = (const float*)d_in[8];
    const float* b_n2a  = (const float*)d_in[9];
    const float* w_n2b  = (const float*)d_in[10];
    const float* b_n2b  = (const float*)d_in[11];
    const float* w_g    = (const float*)d_in[12];  // [H,4D,D]
    const float* b_g    = (const float*)d_in[13];
    const float* w_o    = (const float*)d_in[14];  // [H,2D,D]
    const float* b_o    = (const float*)d_in[15];

    float* out     = (float*)d_out;
    float* out_gnn = out;                                    // [S,B,D]
    float* out_ne  = out + (size_t)SS*BB*DD;                 // [B,N,D]
    float* out_po  = out_ne + (size_t)BB*NN*DD;              // [B,D]

    float *g_gt, *g_lt, *nodeA, *nodeB, *t1, *t2, *t3, *t4, *ni1, *ni2, *ninfo, *WT;
    int* invmap;
    cudaGetSymbolAddress((void**)&g_gt,   g_gt_buf);
    cudaGetSymbolAddress((void**)&g_lt,   g_lt_buf);
    cudaGetSymbolAddress((void**)&invmap, invmap_buf);
    cudaGetSymbolAddress((void**)&nodeA,  buf_nodeA);
    cudaGetSymbolAddress((void**)&nodeB,  buf_nodeB);
    cudaGetSymbolAddress((void**)&t1,     buf_t1);
    cudaGetSymbolAddress((void**)&t2,     buf_t2);
    cudaGetSymbolAddress((void**)&t3,     buf_t3);
    cudaGetSymbolAddress((void**)&t4,     buf_t4);
    cudaGetSymbolAddress((void**)&ni1,    buf_ni1);
    cudaGetSymbolAddress((void**)&ni2,    buf_ni2);
    cudaGetSymbolAddress((void**)&ninfo,  buf_ninfo);
    cudaGetSymbolAddress((void**)&WT,     buf_WT);

    cudaFuncSetAttribute(gemm_mma<0>, cudaFuncAttributeMaxDynamicSharedMemorySize, SMEM_DYN);
    cudaFuncSetAttribute(gemm_mma<1>, cudaFuncAttributeMaxDynamicSharedMemorySize, SMEM_DYN);

    build_graphs_inv<<<BB, NN*NN>>>(order, pos, g_gt, g_lt, invmap);

    // all weight transposes in one launch
    {
        TArgs TA;
        for (int h = 0; h < HH; h++) {
            float* base = WT + (size_t)h*8*DD*DD;
            TJob* j = TA.j + h*7;
            j[0] = { w_n1a + (size_t)h*DD*DD, base + 0*(size_t)DD*DD, nullptr, 0 };
            j[1] = { w_n1b + (size_t)h*DD*DD, base + 1*(size_t)DD*DD, nullptr, 0 };
            j[2] = { w_n2a + (size_t)h*DD*DD, base + 2*(size_t)DD*DD, nullptr, 0 };
            j[3] = { w_n2b + (size_t)h*DD*DD, base + 3*(size_t)DD*DD, nullptr, 0 };
            j[4] = { w_o + (size_t)h*2*DD*DD,                  base + 6*(size_t)DD*DD, nullptr, 0 };
            j[5] = { w_o + (size_t)h*2*DD*DD + (size_t)DD*DD,  base + 7*(size_t)DD*DD, nullptr, 0 };
            j[6] = { w_g + (size_t)h*4*DD*DD, base + 4*(size_t)DD*DD, base + 5*(size_t)DD*DD, 1 };
        }
        transpose_all<<<dim3(16,16,14), dim3(32,8)>>>(TA);
    }

    const dim3 ggrid(4, 32, 2);   // N tiles, M tiles, pair
    const float* node = numenc;   // hop-0 input read directly
    float* nodeOut[2] = { nodeA, nodeB };

    for (int h = 0; h < HH; h++) {
        float* base = WT + (size_t)h*8*DD*DD;

        // u1 = g_gt @ node, u2 = g_lt @ node
        graph_agg2<<<dim3(BB,4,2), 128>>>(g_gt, g_lt, node, node, t1, t2);

        // v1 = relu(u1@w1a + b), v2 = relu(u2@w2a + b)
        {
            GemmPair P = {};
            P.A[0]=t1; P.W[0]=base+0*(size_t)DD*DD; P.bias[0]=b_n1a+h*DD; P.out[0]=t3;
            P.A[1]=t2; P.W[1]=base+2*(size_t)DD*DD; P.bias[1]=b_n2a+h*DD; P.out[1]=t4;
            gemm_mma<1><<<ggrid, 256, SMEM_DYN>>>(P);
        }

        // u1b = g_gt @ v1, u2b = g_lt @ v2
        graph_agg2<<<dim3(BB,4,2), 128>>>(g_gt, g_lt, t3, t4, t1, t2);

        // ni1 = relu(u1b@w1b + b), ni2 = relu(u2b@w2b + b)
        {
            GemmPair P = {};
            P.A[0]=t1; P.W[0]=base+1*(size_t)DD*DD; P.bias[0]=b_n1b+h*DD; P.out[0]=ni1;
            P.A[1]=t2; P.W[1]=base+3*(size_t)DD*DD; P.bias[1]=b_n2b+h*DD; P.out[1]=ni2;
            gemm_mma<1><<<ggrid, 256, SMEM_DYN>>>(P);
        }

        // gate partials: p0 = ni1@Wg1, p1 = ni2@Wg2  (raw)
        {
            GemmPair P = {};
            P.A[0]=ni1; P.W[0]=base+4*(size_t)DD*DD; P.out[0]=t3;
            P.A[1]=ni2; P.W[1]=base+5*(size_t)DD*DD; P.out[1]=t4;
            gemm_mma<0><<<ggrid, 256, SMEM_DYN>>>(P);
        }
        // ninfo = sig(p0+p1+b_g)*ni1 + (1-sig)*ni2
        combine_gate<<<MM*DD/4/256, 256>>>((const float4*)t3, (const float4*)t4,
                                           (const float4*)(b_g + h*DD),
                                           (const float4*)ni1, (const float4*)ni2,
                                           (float4*)ninfo);

        // output partials: p0 = node@woA, p1 = ninfo@woB (raw)
        {
            GemmPair P = {};
            P.A[0]=node;  P.W[0]=base+6*(size_t)DD*DD; P.out[0]=t3;
            P.A[1]=ninfo; P.W[1]=base+7*(size_t)DD*DD; P.out[1]=t4;
            gemm_mma<0><<<ggrid, 256, SMEM_DYN>>>(P);
        }
        // node' = relu(p0+p1+b_o); last hop also writes out_ne = numenc + node'
        combine_relu<<<MM*DD/4/256, 256>>>((const float4*)t3, (const float4*)t4,
                                           (const float4*)(b_o + h*DD),
                                           (float4*)nodeOut[h],
                                           (h == HH-1) ? (const float4*)numenc : nullptr,
                                           (float4*)out_ne);
        node = nodeOut[h];
    }

    fused_assemble<<<dim3(BB,4), 128>>>(enc, node, invmap, out_gnn, out_po);
}

// round 7
// speedup vs baseline: 1.4173x; 1.3169x over previous
#include <cuda_runtime.h>
#include <cuda_fp16.h>
#include <math.h>
#include <stdint.h>

#define BB 128
#define SS 512
#define NN 32
#define DD 512
#define HH 2
#define MM (BB*NN)   // 4096 rows

#define KCH 64                  // fp16 elements per pipeline chunk (128 B/row)
#define HPITCH 72               // smem row pitch in halves (144 B, conflict-free ldsm)
#define ABYTES (128*HPITCH*2)   // 18432 per matrix per stage
#define STGB (2*ABYTES)         // 36864 per stage (A+B)
#define NSTG 3
#define SMEM_DYN (NSTG*STGB)    // 110592 -> 2 CTAs/SM

// ---------------- scratch (device globals; no allocation) ----------------
__device__ float g_gt_buf[BB*NN*NN];
__device__ float g_lt_buf[BB*NN*NN];
__device__ int   invmap_buf[BB*SS];
__device__ float  buf_p0[MM*DD];          // fp32 split-K partials
__device__ float  buf_p1[MM*DD];
__device__ float  buf_nodeF[MM*DD];       // fp32 final node (for assembly)
__device__ __half buf_numencH[MM*DD];
__device__ __half buf_t1h[MM*DD];
__device__ __half buf_t2h[MM*DD];
__device__ __half buf_t3h[MM*DD];
__device__ __half buf_t4h[MM*DD];
__device__ __half buf_ni1h[MM*DD];
__device__ __half buf_ni2h[MM*DD];
__device__ __half buf_ninfoh[MM*DD];
__device__ __half buf_nodeH[2][MM*DD];
__device__ __half buf_WT[16*DD*DD];       // transposed fp16 weights [N,K]

// ---------------- helpers ----------------
__device__ __forceinline__ uint32_t smem_u32(const void* p) {
    return (uint32_t)__cvta_generic_to_shared(p);
}
__device__ __forceinline__ void cp_async16(uint32_t dst, const void* src) {
    asm volatile("cp.async.cg.shared.global [%0], [%1], 16;" :: "r"(dst), "l"(src));
}
__device__ __forceinline__ void mma_f16(float* c, const uint32_t* a,
                                        uint32_t b0, uint32_t b1) {
    asm volatile("mma.sync.aligned.m16n8k16.row.col.f32.f16.f16.f32 "
                 "{%0,%1,%2,%3}, {%4,%5,%6,%7}, {%8,%9}, {%0,%1,%2,%3};"
                 : "+f"(c[0]), "+f"(c[1]), "+f"(c[2]), "+f"(c[3])
                 : "r"(a[0]), "r"(a[1]), "r"(a[2]), "r"(a[3]), "r"(b0), "r"(b1));
}
__device__ __forceinline__ void ldsm_x4(uint32_t addr, uint32_t* r) {
    asm volatile("ldmatrix.sync.aligned.m8n8.x4.shared.b16 {%0,%1,%2,%3}, [%4];"
                 : "=r"(r[0]), "=r"(r[1]), "=r"(r[2]), "=r"(r[3]) : "r"(addr));
}

// ---------------- graph construction (+ invmap) ----------------
__global__ void build_graphs_inv(const int* __restrict__ order, const int* __restrict__ pos,
                                 float* __restrict__ g_gt, float* __restrict__ g_lt,
                                 int* __restrict__ invmap) {
    int b = blockIdx.x;
    __shared__ int ord[NN];
    int tid = threadIdx.x;              // 1024 threads = NN*NN
    if (tid < NN) ord[tid] = order[b*NN + tid];
    if (tid < SS) invmap[b*SS + tid] = -1;
    __syncthreads();
    if (tid < NN) {
        int p = pos[b*NN + tid];
        if (p >= 0) invmap[b*SS + p] = b*NN + tid;
    }
    int n = tid >> 5, m = tid & 31;
    int on = ord[n], om = ord[m];
    float pair = (on > 0 && om > 0 && n != m) ? 1.f : 0.f;
    float eye  = (n == m) ? 1.f : 0.f;
    float vg = pair * ((on > om) ? 1.f : 0.f) + eye;
    float vl = pair * ((on > om) ? 0.f : 1.f) + eye;
    float sg = vg, sl = vl;
    #pragma unroll
    for (int off = 16; off; off >>= 1) {
        sg += __shfl_xor_sync(0xffffffffu, sg, off);
        sl += __shfl_xor_sync(0xffffffffu, sl, off);
    }
    g_gt[b*NN*NN + tid] = vg / sg;
    g_lt[b*NN*NN + tid] = vl / sl;
}

// ---------------- fp32 -> fp16 convert ----------------
__global__ void f2h(const float2* __restrict__ src, __half2* __restrict__ dst, int n2) {
    int i = blockIdx.x*blockDim.x + threadIdx.x;
    int stride = gridDim.x*blockDim.x;
    for (; i < n2; i += stride) dst[i] = __float22half2_rn(src[i]);
}

// ---------------- dual graph aggregation (fp16 in/out) ----------------
__global__ void graph_agg2(const float* __restrict__ g_gt, const float* __restrict__ g_lt,
                           const __half* __restrict__ x0, const __half* __restrict__ x1,
                           __half* __restrict__ y0, __half* __restrict__ y1) {
    int b = blockIdx.x;
    const float* g = blockIdx.z ? g_lt : g_gt;
    const __half* x = blockIdx.z ? x1 : x0;
    __half* y       = blockIdx.z ? y1 : y0;
    int d = blockIdx.y * 128 + threadIdx.x;    // 128 threads
    __shared__ float gs[NN*NN];
    for (int i = threadIdx.x; i < NN*NN; i += 128) gs[i] = g[b*NN*NN + i];
    __syncthreads();
    const __half* xb = x + (size_t)b*NN*DD + d;
    float xv[NN];
    #pragma unroll
    for (int m = 0; m < NN; m++) xv[m] = __half2float(xb[(size_t)m*DD]);
    __half* yb = y + (size_t)b*NN*DD + d;
    #pragma unroll
    for (int n = 0; n < NN; n++) {
        float acc = 0.f;
        #pragma unroll
        for (int m = 0; m < NN; m++) acc = fmaf(gs[n*NN+m], xv[m], acc);
        yb[(size_t)n*DD] = __float2half(acc);
    }
}

// ---------------- single-launch weight transpose ([K,N]->[N,K] fp16) -----------
struct TJob { const float* src; __half* d1; __half* d2; int gate; };
struct TArgs { TJob j[14]; };

__global__ void transpose_all(TArgs A) {
    TJob job = A.j[blockIdx.z];
    __shared__ float t1s[32][33], t2s[32][33];
    int k0 = blockIdx.x*32, n0 = blockIdx.y*32;
    int tx = threadIdx.x, ty = threadIdx.y;
    if (!job.gate) {
        #pragma unroll
        for (int i = 0; i < 4; i++)
            t1s[ty + i*8][tx] = job.src[(size_t)(k0 + ty + i*8)*DD + n0 + tx];
        __syncthreads();
        #pragma unroll
        for (int i = 0; i < 4; i++)
            job.d1[(size_t)(n0 + ty + i*8)*DD + k0 + tx] = __float2half(t1s[tx][ty + i*8]);
    } else {
        #pragma unroll
        for (int i = 0; i < 4; i++) {
            int k = k0 + ty + i*8, n = n0 + tx;
            float w0 = job.src[(size_t)k*DD + n];
            float w1 = job.src[(size_t)(DD + k)*DD + n];
            float w2 = job.src[(size_t)(2*DD + k)*DD + n];
            float w3 = job.src[(size_t)(3*DD + k)*DD + n];
            t1s[ty + i*8][tx] = w0 + w2 + w3;
            t2s[ty + i*8][tx] = w1 + w2 - w3;
        }
        __syncthreads();
        #pragma unroll
        for (int i = 0; i < 4; i++) {
            size_t o = (size_t)(n0 + ty + i*8)*DD + k0 + tx;
            job.d1[o] = __float2half(t1s[tx][ty + i*8]);
            job.d2[o] = __float2half(t2s[tx][ty + i*8]);
        }
    }
}

// ---------------- FP16 mma.sync GEMM ----------------
// out_z = epi(A_z @ W_z^T [+ bias_z]); EPI 0: raw fp32 partials, EPI 1: bias+relu fp16
struct GemmPair {
    const __half *A[2], *W[2];
    const float *bias[2];
    float  *outF[2];
    __half *outH[2];
};

__device__ __forceinline__ void load_chunk(uint32_t smbase, const __half* Asrc,
                                           const __half* Wsrc, int bm, int bn,
                                           int kk, int tid) {
    #pragma unroll
    for (int j = 0; j < 4; j++) {
        int f = tid + 256*j; int row = f >> 3, c = f & 7;
        cp_async16(smbase + row*(HPITCH*2) + c*16,
                   Asrc + (size_t)(bm + row)*512 + kk + c*8);
    }
    #pragma unroll
    for (int j = 0; j < 4; j++) {
        int f = tid + 256*j; int row = f >> 3, c = f & 7;
        cp_async16(smbase + ABYTES + row*(HPITCH*2) + c*16,
                   Wsrc + (size_t)(bn + row)*512 + kk + c*8);
    }
}

template<int EPI>
__global__ void __launch_bounds__(256, 2)
gemm_mma(GemmPair P, int nK)
{
    const int z = blockIdx.z;
    const __half* A = P.A[z]; const __half* W = P.W[z];
    const float* bias = P.bias[z];
    float*  outF = P.outF[z];
    __half* outH = P.outH[z];

    extern __shared__ char sm[];
    const int bm = blockIdx.y * 128, bn = blockIdx.x * 128;
    const int tid = threadIdx.x, wid = tid >> 5, lane = tid & 31;
    const int wm = (wid >> 1) * 32, wn = (wid & 1) * 64;

    // ldmatrix lane addressing (bytes); quadrant col offset = 16 B (8 halves)
    const int laneAr = (lane & 7) + ((lane & 8) ? 8 : 0);
    const int laneAc = (lane & 16) ? 8 : 0;
    const int laneBr = (lane & 7) + ((lane & 16) ? 8 : 0);
    const int laneBc = (lane & 8) ? 8 : 0;
    const uint32_t smb = smem_u32(sm);
    uint32_t aAddr[2], bAddr[4];
    #pragma unroll
    for (int mi = 0; mi < 2; mi++)
        aAddr[mi] = smb + ((wm + mi*16 + laneAr)*HPITCH + laneAc)*2;
    #pragma unroll
    for (int p = 0; p < 4; p++)
        bAddr[p] = smb + ABYTES + ((wn + p*16 + laneBr)*HPITCH + laneBc)*2;

    float acc[2][8][4];
    #pragma unroll
    for (int i = 0; i < 2; i++)
        #pragma unroll
        for (int j = 0; j < 8; j++)
            #pragma unroll
            for (int q = 0; q < 4; q++) acc[i][j][q] = 0.f;

    const int NC = nK >> 6;

    // prologue: chunks 0,1 -> stages 0,1   (chunk k<512 uses A/W via kk mask)
    load_chunk(smb, A, W, bm, bn, 0, tid);
    asm volatile("cp.async.commit_group;");
    load_chunk(smb + STGB, A, W, bm, bn, KCH, tid);
    asm volatile("cp.async.commit_group;");

    int rs = 0, ws = 2;
    #pragma unroll 1
    for (int kc = 0; kc < NC; kc++) {
        if (kc + 1 < NC) asm volatile("cp.async.wait_group 1;");
        else             asm volatile("cp.async.wait_group 0;");
        __syncthreads();

        if (kc + 2 < NC) {
            load_chunk(smb + ws*STGB, A, W, bm, bn, (kc + 2)*KCH, tid);
            asm volatile("cp.async.commit_group;");
        }

        const uint32_t soff = (uint32_t)rs * STGB;
        #pragma unroll
        for (int s4 = 0; s4 < 4; s4++) {           // 4 x k16
            const uint32_t koff = soff + s4*32;    // 16 halves = 32 B
            uint32_t aF[2][4], bF[4][4];
            ldsm_x4(aAddr[0] + koff, aF[0]);
            ldsm_x4(aAddr[1] + koff, aF[1]);
            #pragma unroll
            for (int p = 0; p < 4; p++) ldsm_x4(bAddr[p] + koff, bF[p]);
            #pragma unroll
            for (int p = 0; p < 4; p++) {
                mma_f16(acc[0][2*p],   aF[0], bF[p][0], bF[p][1]);
                mma_f16(acc[1][2*p],   aF[1], bF[p][0], bF[p][1]);
                mma_f16(acc[0][2*p+1], aF[0], bF[p][2], bF[p][3]);
                mma_f16(acc[1][2*p+1], aF[1], bF[p][2], bF[p][3]);
            }
        }
        rs = (rs + 1 == NSTG) ? 0 : rs + 1;
        ws = (ws + 1 == NSTG) ? 0 : ws + 1;
    }

    // epilogue
    const int r0 = bm + wm + (lane >> 2);
    const int cbase = bn + wn + (lane & 3)*2;
    float bb0[8], bb1[8];
    if (EPI == 1) {
        #pragma unroll
        for (int ni = 0; ni < 8; ni++) {
            bb0[ni] = bias[cbase + ni*8];
            bb1[ni] = bias[cbase + ni*8 + 1];
        }
    }
    #pragma unroll
    for (int mi = 0; mi < 2; mi++) {
        int row0 = r0 + mi*16, row1 = row0 + 8;
        #pragma unroll
        for (int ni = 0; ni < 8; ni++) {
            int col = cbase + ni*8;
            float v0 = acc[mi][ni][0], v1 = acc[mi][ni][1];
            float v2 = acc[mi][ni][2], v3 = acc[mi][ni][3];
            if (EPI == 1) {
                v0 = fmaxf(v0 + bb0[ni], 0.f); v1 = fmaxf(v1 + bb1[ni], 0.f);
                v2 = fmaxf(v2 + bb0[ni], 0.f); v3 = fmaxf(v3 + bb1[ni], 0.f);
                *(__half2*)(outH + (size_t)row0*512 + col) = __floats2half2_rn(v0, v1);
                *(__half2*)(outH + (size_t)row1*512 + col) = __floats2half2_rn(v2, v3);
            } else {
                *(float2*)(outF + (size_t)row0*512 + col) = make_float2(v0, v1);
                *(float2*)(outF + (size_t)row1*512 + col) = make_float2(v2, v3);
            }
        }
    }
}

// ---------------- split-K combine kernels ----------------
// gate: ninfo = sig(p0+p1+bias)*e1 + (1-sig)*e2   (fp16 e, fp16 out)
__global__ void combine_gate(const float4* __restrict__ p0, const float4* __restrict__ p1,
                             const float4* __restrict__ bias,
                             const __half2* __restrict__ e1, const __half2* __restrict__ e2,
                             __half2* __restrict__ out) {
    int i = blockIdx.x*256 + threadIdx.x;       // MM*DD/4
    float4 a = p0[i], b = p1[i], bi = bias[i & 127];
    float2 x0 = __half22float2(e1[2*i]),   x1 = __half22float2(e1[2*i+1]);
    float2 y0 = __half22float2(e2[2*i]),   y1 = __half22float2(e2[2*i+1]);
    float g0 = 1.f/(1.f + expf(-(a.x + b.x + bi.x)));
    float g1 = 1.f/(1.f + expf(-(a.y + b.y + bi.y)));
    float g2 = 1.f/(1.f + expf(-(a.z + b.z + bi.z)));
    float g3 = 1.f/(1.f + expf(-(a.w + b.w + bi.w)));
    out[2*i]   = __floats2half2_rn(g0*x0.x + (1.f-g0)*y0.x, g1*x0.y + (1.f-g1)*y0.y);
    out[2*i+1] = __floats2half2_rn(g2*x1.x + (1.f-g2)*y1.x, g3*x1.y + (1.f-g3)*y1.y);
}

// relu: node = relu(p0+p1+bias) -> fp16 nodeH + fp32 nodeF; optional out2 = addsrc+node
__global__ void combine_relu(const float4* __restrict__ p0, const float4* __restrict__ p1,
                             const float4* __restrict__ bias,
                             __half2* __restrict__ outH, float4* __restrict__ outF,
                             const float4* __restrict__ addsrc, float4* __restrict__ out2) {
    int i = blockIdx.x*256 + threadIdx.x;
    float4 a = p0[i], b = p1[i], bi = bias[i & 127];
    float4 v = make_float4(fmaxf(a.x + b.x + bi.x, 0.f), fmaxf(a.y + b.y + bi.y, 0.f),
                           fmaxf(a.z + b.z + bi.z, 0.f), fmaxf(a.w + b.w + bi.w, 0.f));
    outH[2*i]   = __floats2half2_rn(v.x, v.y);
    outH[2*i+1] = __floats2half2_rn(v.z, v.w);
    outF[i] = v;
    if (addsrc) {
        float4 s = addsrc[i];
        out2[i] = make_float4(s.x + v.x, s.y + v.y, s.z + v.z, s.w + v.w);
    }
}

// gnn[s,b,:] = enc[s,b,:] + scattered node; po[b,:] = max_s gnn[s,b,:]
__global__ void fused_assemble(const float* __restrict__ enc, const float* __restrict__ node,
                               const int* __restrict__ invmap,
                               float* __restrict__ gnn, float* __restrict__ po) {
    int b = blockIdx.x;
    int d = blockIdx.y * 128 + threadIdx.x;
    __shared__ int inv[SS];
    for (int i = threadIdx.x; i < SS; i += 128) inv[i] = invmap[b*SS + i];
    __syncthreads();
    size_t base = (size_t)b*DD + d;
    float m = -3.402823466e38f;
    #pragma unroll 1
    for (int s = 0; s < SS; s += 4) {
        float v[4];
        #pragma unroll
        for (int u = 0; u < 4; u++)
            v[u] = enc[(size_t)(s + u)*BB*DD + base];
        #pragma unroll
        for (int u = 0; u < 4; u++) {
            int iv = inv[s + u];
            if (iv >= 0) v[u] += node[(size_t)iv*DD + d];
        }
        #pragma unroll
        for (int u = 0; u < 4; u++) {
            gnn[(size_t)(s + u)*BB*DD + base] = v[u];
            m = fmaxf(m, v[u]);
        }
    }
    po[base] = m;
}

// ---------------- host launch ----------------
extern "C" void kernel_launch(void* const* d_in, const int* in_sizes, int n_in,
                              void* d_out, int out_size) {
    const float* enc    = (const float*)d_in[0];   // [S,B,D]
    const float* numenc = (const float*)d_in[1];   // [B,N,D]
    const int*   pos    = (const int*)d_in[2];     // [B,N]
    const int*   order  = (const int*)d_in[3];     // [B,N]
    const float* w_n1a  = (const float*)d_in[4];
    const float* b_n1a  = (const float*)d_in[5];
    const float* w_n1b  = (const float*)d_in[6];
    const float* b_n1b  = (const float*)d_in[7];
    const float* w_n2a  = (const float*)d_in[8];
    const float* b_n2a  = (const float*)d_in[9];
    const float* w_n2b  = (const float*)d_in[10];
    const float* b_n2b  = (const float*)d_in[11];
    const float* w_g    = (const float*)d_in[12];  // [H,4D,D]
    const float* b_g    = (const float*)d_in[13];
    const float* w_o    = (const float*)d_in[14];  // [H,2D,D]
    const float* b_o    = (const float*)d_in[15];

    float* out     = (float*)d_out;
    float* out_gnn = out;                                    // [S,B,D]
    float* out_ne  = out + (size_t)SS*BB*DD;                 // [B,N,D]
    float* out_po  = out_ne + (size_t)BB*NN*DD;              // [B,D]

    float *g_gt, *g_lt, *p0, *p1, *nodeF;
    __half *numencH, *t1h, *t2h, *t3h, *t4h, *ni1h, *ni2h, *ninfoh, *nodeH0, *nodeH1, *WT;
    int* invmap;
    cudaGetSymbolAddress((void**)&g_gt,    g_gt_buf);
    cudaGetSymbolAddress((void**)&g_lt,    g_lt_buf);
    cudaGetSymbolAddress((void**)&invmap,  invmap_buf);
    cudaGetSymbolAddress((void**)&p0,      buf_p0);
    cudaGetSymbolAddress((void**)&p1,      buf_p1);
    cudaGetSymbolAddress((void**)&nodeF,   buf_nodeF);
    cudaGetSymbolAddress((void**)&numencH, buf_numencH);
    cudaGetSymbolAddress((void**)&t1h,     buf_t1h);
    cudaGetSymbolAddress((void**)&t2h,     buf_t2h);
    cudaGetSymbolAddress((void**)&t3h,     buf_t3h);
    cudaGetSymbolAddress((void**)&t4h,     buf_t4h);
    cudaGetSymbolAddress((void**)&ni1h,    buf_ni1h);
    cudaGetSymbolAddress((void**)&ni2h,    buf_ni2h);
    cudaGetSymbolAddress((void**)&ninfoh,  buf_ninfoh);
    cudaGetSymbolAddress((void**)&nodeH0,  buf_nodeH);      // [0]
    nodeH1 = nodeH0 + (size_t)MM*DD;                        // [1]
    cudaGetSymbolAddress((void**)&WT,      buf_WT);

    cudaFuncSetAttribute(gemm_mma<0>, cudaFuncAttributeMaxDynamicSharedMemorySize, SMEM_DYN);
    cudaFuncSetAttribute(gemm_mma<1>, cudaFuncAttributeMaxDynamicSharedMemorySize, SMEM_DYN);

    build_graphs_inv<<<BB, NN*NN>>>(order, pos, g_gt, g_lt, invmap);
    f2h<<<512, 256>>>((const float2*)numenc, (__half2*)numencH, MM*DD/2);

    // all weight transposes in one launch (fp16 [N,K])
    {
        TArgs TA;
        for (int h = 0; h < HH; h++) {
            __half* base = WT + (size_t)h*8*DD*DD;
            TJob* j = TA.j + h*7;
            j[0] = { w_n1a + (size_t)h*DD*DD, base + 0*(size_t)DD*DD, nullptr, 0 };
            j[1] = { w_n1b + (size_t)h*DD*DD, base + 1*(size_t)DD*DD, nullptr, 0 };
            j[2] = { w_n2a + (size_t)h*DD*DD, base + 2*(size_t)DD*DD, nullptr, 0 };
            j[3] = { w_n2b + (size_t)h*DD*DD, base + 3*(size_t)DD*DD, nullptr, 0 };
            j[4] = { w_o + (size_t)h*2*DD*DD,                  base + 6*(size_t)DD*DD, nullptr, 0 };
            j[5] = { w_o + (size_t)h*2*DD*DD + (size_t)DD*DD,  base + 7*(size_t)DD*DD, nullptr, 0 };
            j[6] = { w_g + (size_t)h*4*DD*DD, base + 4*(size_t)DD*DD, base + 5*(size_t)DD*DD, 1 };
        }
        transpose_all<<<dim3(16,16,14), dim3(32,8)>>>(TA);
    }

    const dim3 ggrid(4, 32, 2);   // N tiles, M tiles, pair
    const __half* node = numencH;
    __half* nodeOutH[2] = { nodeH0, nodeH1 };

    for (int h = 0; h < HH; h++) {
        __half* base = WT + (size_t)h*8*DD*DD;

        // u1 = g_gt @ node, u2 = g_lt @ node
        graph_agg2<<<dim3(BB,4,2), 128>>>(g_gt, g_lt, node, node, t1h, t2h);

        // v1 = relu(u1@w1a + b), v2 = relu(u2@w2a + b)
        {
            GemmPair P = {};
            P.A[0]=t1h; P.W[0]=base+0*(size_t)DD*DD; P.bias[0]=b_n1a+h*DD; P.outH[0]=t3h;
            P.A[1]=t2h; P.W[1]=base+2*(size_t)DD*DD; P.bias[1]=b_n2a+h*DD; P.outH[1]=t4h;
            gemm_mma<1><<<ggrid, 256, SMEM_DYN>>>(P, 512);
        }

        // u1b = g_gt @ v1, u2b = g_lt @ v2
        graph_agg2<<<dim3(BB,4,2), 128>>>(g_gt, g_lt, t3h, t4h, t1h, t2h);

        // ni1 = relu(u1b@w1b + b), ni2 = relu(u2b@w2b + b)
        {
            GemmPair P = {};
            P.A[0]=t1h; P.W[0]=base+1*(size_t)DD*DD; P.bias[0]=b_n1b+h*DD; P.outH[0]=ni1h;
            P.A[1]=t2h; P.W[1]=base+3*(size_t)DD*DD; P.bias[1]=b_n2b+h*DD; P.outH[1]=ni2h;
            gemm_mma<1><<<ggrid, 256, SMEM_DYN>>>(P, 512);
        }

        // gate partials: p0 = ni1@Wg1, p1 = ni2@Wg2
        {
            GemmPair P = {};
            P.A[0]=ni1h; P.W[0]=base+4*(size_t)DD*DD; P.outF[0]=p0;
            P.A[1]=ni2h; P.W[1]=base+5*(size_t)DD*DD; P.outF[1]=p1;
            gemm_mma<0><<<ggrid, 256, SMEM_DYN>>>(P, 512);
        }
        // ninfo = sig(p0+p1+b_g)*ni1 + (1-sig)*ni2
        combine_gate<<<MM*DD/4/256, 256>>>((const float4*)p0, (const float4*)p1,
                                           (const float4*)(b_g + h*DD),
                                           (const __half2*)ni1h, (const __half2*)ni2h,
                                           (__half2*)ninfoh);

        // output partials: p0 = node@woA, p1 = ninfo@woB
        {
            GemmPair P = {};
            P.A[0]=node;   P.W[0]=base+6*(size_t)DD*DD; P.outF[0]=p0;
            P.A[1]=ninfoh; P.W[1]=base+7*(size_t)DD*DD; P.outF[1]=p1;
            gemm_mma<0><<<ggrid, 256, SMEM_DYN>>>(P, 512);
        }
        // node' = relu(p0+p1+b_o); last hop also writes out_ne = numenc + node'
        combine_relu<<<MM*DD/4/256, 256>>>((const float4*)p0, (const float4*)p1,
                                           (const float4*)(b_o + h*DD),
                                           (__half2*)nodeOutH[h], (float4*)nodeF,
                                           (h == HH-1) ? (const float4*)numenc : nullptr,
                                           (float4*)out_ne);
        node = nodeOutH[h];
    }

    fused_assemble<<<dim3(BB,4), 128>>>(enc, nodeF, invmap, out_gnn, out_po);
}

// round 8
// speedup vs baseline: 1.6892x; 1.1918x over previous
#include <cuda_runtime.h>
#include <cuda_fp16.h>
#include <math.h>
#include <stdint.h>

#define BB 128
#define SS 512
#define NN 32
#define DD 512
#define HH 2
#define MM (BB*NN)   // 4096 rows

#define KCH 64                  // fp16 elements per pipeline chunk (128 B/row)
#define HPITCH 72               // smem row pitch in halves (144 B, conflict-free ldsm)
#define ABYTES (128*HPITCH*2)   // 18432 per matrix per stage
#define STGB (2*ABYTES)         // 36864 per stage (A+B)
#define NSTG 3
#define SMEM_DYN (NSTG*STGB)    // 110592 -> 2 CTAs/SM

// ---------------- scratch (device globals; no allocation) ----------------
__device__ int   invmap_buf[BB*SS];
__device__ int   perm_buf[BB*NN];
__device__ int   V_buf[BB];
__device__ float  buf_p0[MM*DD];          // fp32 split-K partials (+ po_part reuse)
__device__ float  buf_p1[MM*DD];
__device__ float  buf_nodeF[MM*DD];       // fp32 final node (for assembly)
__device__ __half buf_numencH[MM*DD];
__device__ __half buf_t1h[MM*DD];
__device__ __half buf_t2h[MM*DD];
__device__ __half buf_t3h[MM*DD];
__device__ __half buf_t4h[MM*DD];
__device__ __half buf_ni1h[MM*DD];
__device__ __half buf_ni2h[MM*DD];
__device__ __half buf_ninfoh[MM*DD];
__device__ __half buf_nodeH[2][MM*DD];
__device__ __half buf_WT[16*DD*DD];       // transposed fp16 weights [N,K]

// ---------------- helpers ----------------
__device__ __forceinline__ uint32_t smem_u32(const void* p) {
    return (uint32_t)__cvta_generic_to_shared(p);
}
__device__ __forceinline__ void cp_async16(uint32_t dst, const void* src) {
    asm volatile("cp.async.cg.shared.global [%0], [%1], 16;" :: "r"(dst), "l"(src));
}
__device__ __forceinline__ void mma_f16(float* c, const uint32_t* a,
                                        uint32_t b0, uint32_t b1) {
    asm volatile("mma.sync.aligned.m16n8k16.row.col.f32.f16.f16.f32 "
                 "{%0,%1,%2,%3}, {%4,%5,%6,%7}, {%8,%9}, {%0,%1,%2,%3};"
                 : "+f"(c[0]), "+f"(c[1]), "+f"(c[2]), "+f"(c[3])
                 : "r"(a[0]), "r"(a[1]), "r"(a[2]), "r"(a[3]), "r"(b0), "r"(b1));
}
__device__ __forceinline__ void ldsm_x4(uint32_t addr, uint32_t* r) {
    asm volatile("ldmatrix.sync.aligned.m8n8.x4.shared.b16 {%0,%1,%2,%3}, [%4];"
                 : "=r"(r[0]), "=r"(r[1]), "=r"(r[2]), "=r"(r[3]) : "r"(addr));
}

// ---------------- meta: invmap + rank permutation + valid count ----------------
__global__ void build_meta(const int* __restrict__ order, const int* __restrict__ pos,
                           int* __restrict__ invmap, int* __restrict__ perm,
                           int* __restrict__ Vv) {
    int b = blockIdx.x, tid = threadIdx.x;    // 512 threads
    __shared__ int ord[NN];
    if (tid < NN) ord[tid] = order[b*NN + tid];
    invmap[b*SS + tid] = -1;
    __syncthreads();
    if (tid < NN) {
        int p = pos[b*NN + tid];
        if (p >= 0) invmap[b*SS + p] = b*NN + tid;
        int o = ord[tid];
        bool valid = o > 0;
        int cntLess = 0, cntValid = 0, cntPadB = 0;
        #pragma unroll
        for (int m = 0; m < NN; m++) {
            int om = ord[m];
            bool vm = om > 0;
            cntValid += vm ? 1 : 0;
            cntLess  += (vm && om < o) ? 1 : 0;
            cntPadB  += (!vm && m < tid) ? 1 : 0;
        }
        int r = valid ? cntLess : (cntValid + cntPadB);
        perm[b*NN + r] = tid;
        if (tid == 0) Vv[b] = cntValid;   // recompute below for thread 0 correctness
    }
    // thread 0 wrote cntValid computed in its own loop (same for all threads)
}

// ---------------- fp32 -> fp16 convert ----------------
__global__ void f2h(const float2* __restrict__ src, __half2* __restrict__ dst, int n2) {
    int i = blockIdx.x*blockDim.x + threadIdx.x;
    int stride = gridDim.x*blockDim.x;
    for (; i < n2; i += stride) dst[i] = __float22half2_rn(src[i]);
}

// ---------------- dual graph aggregation via prefix/suffix sums ----------------
// y1 = g_gt @ x0, y2 = g_lt @ x1  (per batch; rank-sorted running sums)
__global__ void __launch_bounds__(256)
graph_agg2(const __half2* __restrict__ x0, const __half2* __restrict__ x1,
           __half2* __restrict__ y1, __half2* __restrict__ y2,
           const int* __restrict__ perm, const int* __restrict__ Vv) {
    int b = blockIdx.x, t = threadIdx.x;       // 256 threads, one half2 col each
    __shared__ int pm[NN];
    __shared__ int Vs;
    if (t < NN) pm[t] = perm[b*NN + t];
    if (t == 0) Vs = Vv[b];
    __syncthreads();
    const int V = Vs;
    const size_t base = (size_t)b*NN*256 + t;

    float2 xv[NN];
    // ---- phase 1: gt prefix on x0 -> y1 (rank order) ----
    #pragma unroll
    for (int rr = 0; rr < NN; rr++)
        xv[rr] = __half22float2(x0[base + (size_t)pm[rr]*256]);
    float2 run = make_float2(0.f, 0.f);
    #pragma unroll
    for (int rr = 0; rr < NN; rr++) {
        const float inv = 1.f/(float)(rr + 1);
        float2 o;
        if (rr < V) {
            o.x = (run.x + xv[rr].x) * inv;
            o.y = (run.y + xv[rr].y) * inv;
            run.x += xv[rr].x; run.y += xv[rr].y;
        } else {
            o = xv[rr];
        }
        y1[base + (size_t)pm[rr]*256] = __floats2half2_rn(o.x, o.y);
    }
    // ---- phase 2: lt suffix on x1 -> y2 (reverse rank order) ----
    #pragma unroll
    for (int rr = 0; rr < NN; rr++) {
        int sr = (rr < V) ? (V - 1 - rr) : rr;
        xv[rr] = __half22float2(x1[base + (size_t)pm[sr]*256]);
    }
    run = make_float2(0.f, 0.f);
    #pragma unroll
    for (int rr = 0; rr < NN; rr++) {
        const float inv = 1.f/(float)(rr + 1);
        int sr = (rr < V) ? (V - 1 - rr) : rr;
        float2 o;
        if (rr < V) {
            o.x = (run.x + xv[rr].x) * inv;
            o.y = (run.y + xv[rr].y) * inv;
            run.x += xv[rr].x; run.y += xv[rr].y;
        } else {
            o = xv[rr];
        }
        y2[base + (size_t)pm[sr]*256] = __floats2half2_rn(o.x, o.y);
    }
}

// ---------------- single-launch weight transpose ([K,N]->[N,K] fp16) -----------
struct TJob { const float* src; __half* d1; __half* d2; int gate; };
struct TArgs { TJob j[14]; };

__global__ void transpose_all(TArgs A) {
    TJob job = A.j[blockIdx.z];
    __shared__ float t1s[32][33], t2s[32][33];
    int k0 = blockIdx.x*32, n0 = blockIdx.y*32;
    int tx = threadIdx.x, ty = threadIdx.y;
    if (!job.gate) {
        #pragma unroll
        for (int i = 0; i < 4; i++)
            t1s[ty + i*8][tx] = job.src[(size_t)(k0 + ty + i*8)*DD + n0 + tx];
        __syncthreads();
        #pragma unroll
        for (int i = 0; i < 4; i++)
            job.d1[(size_t)(n0 + ty + i*8)*DD + k0 + tx] = __float2half(t1s[tx][ty + i*8]);
    } else {
        #pragma unroll
        for (int i = 0; i < 4; i++) {
            int k = k0 + ty + i*8, n = n0 + tx;
            float w0 = job.src[(size_t)k*DD + n];
            float w1 = job.src[(size_t)(DD + k)*DD + n];
            float w2 = job.src[(size_t)(2*DD + k)*DD + n];
            float w3 = job.src[(size_t)(3*DD + k)*DD + n];
            t1s[ty + i*8][tx] = w0 + w2 + w3;
            t2s[ty + i*8][tx] = w1 + w2 - w3;
        }
        __syncthreads();
        #pragma unroll
        for (int i = 0; i < 4; i++) {
            size_t o = (size_t)(n0 + ty + i*8)*DD + k0 + tx;
            job.d1[o] = __float2half(t1s[tx][ty + i*8]);
            job.d2[o] = __float2half(t2s[tx][ty + i*8]);
        }
    }
}

// ---------------- FP16 mma.sync GEMM ----------------
// out_z = epi(A_z @ W_z^T [+ bias_z]); EPI 0: raw fp32 partials, EPI 1: bias+relu fp16
struct GemmPair {
    const __half *A[2], *W[2];
    const float *bias[2];
    float  *outF[2];
    __half *outH[2];
};

__device__ __forceinline__ void load_chunk(uint32_t smbase, const __half* Asrc,
                                           const __half* Wsrc, int bm, int bn,
                                           int kk, int tid) {
    #pragma unroll
    for (int j = 0; j < 4; j++) {
        int f = tid + 256*j; int row = f >> 3, c = f & 7;
        cp_async16(smbase + row*(HPITCH*2) + c*16,
                   Asrc + (size_t)(bm + row)*512 + kk + c*8);
    }
    #pragma unroll
    for (int j = 0; j < 4; j++) {
        int f = tid + 256*j; int row = f >> 3, c = f & 7;
        cp_async16(smbase + ABYTES + row*(HPITCH*2) + c*16,
                   Wsrc + (size_t)(bn + row)*512 + kk + c*8);
    }
}

template<int EPI>
__global__ void __launch_bounds__(256, 2)
gemm_mma(GemmPair P)
{
    const int z = blockIdx.z;
    const __half* A = P.A[z]; const __half* W = P.W[z];
    const float* bias = P.bias[z];
    float*  outF = P.outF[z];
    __half* outH = P.outH[z];

    extern __shared__ char sm[];
    const int bm = blockIdx.y * 128, bn = blockIdx.x * 128;
    const int tid = threadIdx.x, wid = tid >> 5, lane = tid & 31;
    const int wm = (wid >> 1) * 32, wn = (wid & 1) * 64;

    // ldmatrix lane addressing (bytes); quadrant col offset = 16 B (8 halves)
    const int laneAr = (lane & 7) + ((lane & 8) ? 8 : 0);
    const int laneAc = (lane & 16) ? 8 : 0;
    const int laneBr = (lane & 7) + ((lane & 16) ? 8 : 0);
    const int laneBc = (lane & 8) ? 8 : 0;
    const uint32_t smb = smem_u32(sm);
    uint32_t aAddr[2], bAddr[4];
    #pragma unroll
    for (int mi = 0; mi < 2; mi++)
        aAddr[mi] = smb + ((wm + mi*16 + laneAr)*HPITCH + laneAc)*2;
    #pragma unroll
    for (int p = 0; p < 4; p++)
        bAddr[p] = smb + ABYTES + ((wn + p*16 + laneBr)*HPITCH + laneBc)*2;

    float acc[2][8][4];
    #pragma unroll
    for (int i = 0; i < 2; i++)
        #pragma unroll
        for (int j = 0; j < 8; j++)
            #pragma unroll
            for (int q = 0; q < 4; q++) acc[i][j][q] = 0.f;

    const int NC = 512 / KCH;   // 8

    // prologue: chunks 0,1 -> stages 0,1
    load_chunk(smb, A, W, bm, bn, 0, tid);
    asm volatile("cp.async.commit_group;");
    load_chunk(smb + STGB, A, W, bm, bn, KCH, tid);
    asm volatile("cp.async.commit_group;");

    int rs = 0, ws = 2;
    #pragma unroll 1
    for (int kc = 0; kc < NC; kc++) {
        if (kc + 1 < NC) asm volatile("cp.async.wait_group 1;");
        else             asm volatile("cp.async.wait_group 0;");
        __syncthreads();

        if (kc + 2 < NC) {
            load_chunk(smb + ws*STGB, A, W, bm, bn, (kc + 2)*KCH, tid);
            asm volatile("cp.async.commit_group;");
        }

        const uint32_t soff = (uint32_t)rs * STGB;
        #pragma unroll
        for (int s4 = 0; s4 < 4; s4++) {           // 4 x k16
            const uint32_t koff = soff + s4*32;    // 16 halves = 32 B
            uint32_t aF[2][4], bF[4][4];
            ldsm_x4(aAddr[0] + koff, aF[0]);
            ldsm_x4(aAddr[1] + koff, aF[1]);
            #pragma unroll
            for (int p = 0; p < 4; p++) ldsm_x4(bAddr[p] + koff, bF[p]);
            #pragma unroll
            for (int p = 0; p < 4; p++) {
                mma_f16(acc[0][2*p],   aF[0], bF[p][0], bF[p][1]);
                mma_f16(acc[1][2*p],   aF[1], bF[p][0], bF[p][1]);
                mma_f16(acc[0][2*p+1], aF[0], bF[p][2], bF[p][3]);
                mma_f16(acc[1][2*p+1], aF[1], bF[p][2], bF[p][3]);
            }
        }
        rs = (rs + 1 == NSTG) ? 0 : rs + 1;
        ws = (ws + 1 == NSTG) ? 0 : ws + 1;
    }

    // epilogue
    const int r0 = bm + wm + (lane >> 2);
    const int cbase = bn + wn + (lane & 3)*2;
    float bb0[8], bb1[8];
    if (EPI == 1) {
        #pragma unroll
        for (int ni = 0; ni < 8; ni++) {
            bb0[ni] = bias[cbase + ni*8];
            bb1[ni] = bias[cbase + ni*8 + 1];
        }
    }
    #pragma unroll
    for (int mi = 0; mi < 2; mi++) {
        int row0 = r0 + mi*16, row1 = row0 + 8;
        #pragma unroll
        for (int ni = 0; ni < 8; ni++) {
            int col = cbase + ni*8;
            float v0 = acc[mi][ni][0], v1 = acc[mi][ni][1];
            float v2 = acc[mi][ni][2], v3 = acc[mi][ni][3];
            if (EPI == 1) {
                v0 = fmaxf(v0 + bb0[ni], 0.f); v1 = fmaxf(v1 + bb1[ni], 0.f);
                v2 = fmaxf(v2 + bb0[ni], 0.f); v3 = fmaxf(v3 + bb1[ni], 0.f);
                *(__half2*)(outH + (size_t)row0*512 + col) = __floats2half2_rn(v0, v1);
                *(__half2*)(outH + (size_t)row1*512 + col) = __floats2half2_rn(v2, v3);
            } else {
                *(float2*)(outF + (size_t)row0*512 + col) = make_float2(v0, v1);
                *(float2*)(outF + (size_t)row1*512 + col) = make_float2(v2, v3);
            }
        }
    }
}

// ---------------- split-K combine kernels ----------------
__global__ void combine_gate(const float4* __restrict__ p0, const float4* __restrict__ p1,
                             const float4* __restrict__ bias,
                             const __half2* __restrict__ e1, const __half2* __restrict__ e2,
                             __half2* __restrict__ out) {
    int i = blockIdx.x*256 + threadIdx.x;       // MM*DD/4
    float4 a = p0[i], b = p1[i], bi = bias[i & 127];
    float2 x0 = __half22float2(e1[2*i]),   x1 = __half22float2(e1[2*i+1]);
    float2 y0 = __half22float2(e2[2*i]),   y1 = __half22float2(e2[2*i+1]);
    float g0 = 1.f/(1.f + expf(-(a.x + b.x + bi.x)));
    float g1 = 1.f/(1.f + expf(-(a.y + b.y + bi.y)));
    float g2 = 1.f/(1.f + expf(-(a.z + b.z + bi.z)));
    float g3 = 1.f/(1.f + expf(-(a.w + b.w + bi.w)));
    out[2*i]   = __floats2half2_rn(g0*x0.x + (1.f-g0)*y0.x, g1*x0.y + (1.f-g1)*y0.y);
    out[2*i+1] = __floats2half2_rn(g2*x1.x + (1.f-g2)*y1.x, g3*x1.y + (1.f-g3)*y1.y);
}

__global__ void combine_relu(const float4* __restrict__ p0, const float4* __restrict__ p1,
                             const float4* __restrict__ bias,
                             __half2* __restrict__ outH, float4* __restrict__ outF,
                             const float4* __restrict__ addsrc, float4* __restrict__ out2) {
    int i = blockIdx.x*256 + threadIdx.x;
    float4 a = p0[i], b = p1[i], bi = bias[i & 127];
    float4 v = make_float4(fmaxf(a.x + b.x + bi.x, 0.f), fmaxf(a.y + b.y + bi.y, 0.f),
                           fmaxf(a.z + b.z + bi.z, 0.f), fmaxf(a.w + b.w + bi.w, 0.f));
    outH[2*i]   = __floats2half2_rn(v.x, v.y);
    outH[2*i+1] = __floats2half2_rn(v.z, v.w);
    outF[i] = v;
    if (addsrc) {
        float4 s = addsrc[i];
        out2[i] = make_float4(s.x + v.x, s.y + v.y, s.z + v.z, s.w + v.w);
    }
}

// ---------------- output assembly (float4, s split 4-ways + partial max) -------
__global__ void fused_assemble(const float4* __restrict__ enc,
                               const float4* __restrict__ node,
                               const int* __restrict__ invmap,
                               float4* __restrict__ gnn, float4* __restrict__ po_part) {
    int b = blockIdx.x, q = blockIdx.y, t = threadIdx.x;   // 128 threads
    __shared__ int inv[128];
    inv[t] = invmap[b*SS + q*128 + t];
    __syncthreads();
    float4 m = make_float4(-3.402823466e38f, -3.402823466e38f,
                           -3.402823466e38f, -3.402823466e38f);
    #pragma unroll 4
    for (int si = 0; si < 128; si++) {
        int s = q*128 + si;
        size_t o = ((size_t)s*BB + b)*128 + t;
        float4 v = enc[o];
        int iv = inv[si];
        if (iv >= 0) {
            float4 nv = node[(size_t)iv*128 + t];
            v.x += nv.x; v.y += nv.y; v.z += nv.z; v.w += nv.w;
        }
        gnn[o] = v;
        m.x = fmaxf(m.x, v.x); m.y = fmaxf(m.y, v.y);
        m.z = fmaxf(m.z, v.z); m.w = fmaxf(m.w, v.w);
    }
    po_part[((size_t)q*BB + b)*128 + t] = m;
}

__global__ void reduce_po(const float4* __restrict__ pp, float4* __restrict__ po) {
    int i = blockIdx.x*256 + threadIdx.x;      // BB*DD/4 = 16384
    float4 a = pp[i], b = pp[i + 16384], c = pp[i + 2*16384], d = pp[i + 3*16384];
    po[i] = make_float4(fmaxf(fmaxf(a.x,b.x), fmaxf(c.x,d.x)),
                        fmaxf(fmaxf(a.y,b.y), fmaxf(c.y,d.y)),
                        fmaxf(fmaxf(a.z,b.z), fmaxf(c.z,d.z)),
                        fmaxf(fmaxf(a.w,b.w), fmaxf(c.w,d.w)));
}

// ---------------- host launch ----------------
extern "C" void kernel_launch(void* const* d_in, const int* in_sizes, int n_in,
                              void* d_out, int out_size) {
    const float* enc    = (const float*)d_in[0];   // [S,B,D]
    const float* numenc = (const float*)d_in[1];   // [B,N,D]
    const int*   pos    = (const int*)d_in[2];     // [B,N]
    const int*   order  = (const int*)d_in[3];     // [B,N]
    const float* w_n1a  = (const float*)d_in[4];
    const float* b_n1a  = (const float*)d_in[5];
    const float* w_n1b  = (const float*)d_in[6];
    const float* b_n1b  = (const float*)d_in[7];
    const float* w_n2a  = (const float*)d_in[8];
    const float* b_n2a  = (const float*)d_in[9];
    const float* w_n2b  = (const float*)d_in[10];
    const float* b_n2b  = (const float*)d_in[11];
    const float* w_g    = (const float*)d_in[12];  // [H,4D,D]
    const float* b_g    = (const float*)d_in[13];
    const float* w_o    = (const float*)d_in[14];  // [H,2D,D]
    const float* b_o    = (const float*)d_in[15];

    float* out     = (float*)d_out;
    float* out_gnn = out;                                    // [S,B,D]
    float* out_ne  = out + (size_t)SS*BB*DD;                 // [B,N,D]
    float* out_po  = out_ne + (size_t)BB*NN*DD;              // [B,D]

    float *p0, *p1, *nodeF;
    __half *numencH, *t1h, *t2h, *t3h, *t4h, *ni1h, *ni2h, *ninfoh, *nodeH0, *nodeH1, *WT;
    int *invmap, *perm, *Vv;
    cudaGetSymbolAddress((void**)&invmap,  invmap_buf);
    cudaGetSymbolAddress((void**)&perm,    perm_buf);
    cudaGetSymbolAddress((void**)&Vv,      V_buf);
    cudaGetSymbolAddress((void**)&p0,      buf_p0);
    cudaGetSymbolAddress((void**)&p1,      buf_p1);
    cudaGetSymbolAddress((void**)&nodeF,   buf_nodeF);
    cudaGetSymbolAddress((void**)&numencH, buf_numencH);
    cudaGetSymbolAddress((void**)&t1h,     buf_t1h);
    cudaGetSymbolAddress((void**)&t2h,     buf_t2h);
    cudaGetSymbolAddress((void**)&t3h,     buf_t3h);
    cudaGetSymbolAddress((void**)&t4h,     buf_t4h);
    cudaGetSymbolAddress((void**)&ni1h,    buf_ni1h);
    cudaGetSymbolAddress((void**)&ni2h,    buf_ni2h);
    cudaGetSymbolAddress((void**)&ninfoh,  buf_ninfoh);
    cudaGetSymbolAddress((void**)&nodeH0,  buf_nodeH);
    nodeH1 = nodeH0 + (size_t)MM*DD;
    cudaGetSymbolAddress((void**)&WT,      buf_WT);

    cudaFuncSetAttribute(gemm_mma<0>, cudaFuncAttributeMaxDynamicSharedMemorySize, SMEM_DYN);
    cudaFuncSetAttribute(gemm_mma<1>, cudaFuncAttributeMaxDynamicSharedMemorySize, SMEM_DYN);

    build_meta<<<BB, SS>>>(order, pos, invmap, perm, Vv);
    f2h<<<512, 256>>>((const float2*)numenc, (__half2*)numencH, MM*DD/2);

    // all weight transposes in one launch (fp16 [N,K])
    {
        TArgs TA;
        for (int h = 0; h < HH; h++) {
            __half* base = WT + (size_t)h*8*DD*DD;
            TJob* j = TA.j + h*7;
            j[0] = { w_n1a + (size_t)h*DD*DD, base + 0*(size_t)DD*DD, nullptr, 0 };
            j[1] = { w_n1b + (size_t)h*DD*DD, base + 1*(size_t)DD*DD, nullptr, 0 };
            j[2] = { w_n2a + (size_t)h*DD*DD, base + 2*(size_t)DD*DD, nullptr, 0 };
            j[3] = { w_n2b + (size_t)h*DD*DD, base + 3*(size_t)DD*DD, nullptr, 0 };
            j[4] = { w_o + (size_t)h*2*DD*DD,                  base + 6*(size_t)DD*DD, nullptr, 0 };
            j[5] = { w_o + (size_t)h*2*DD*DD + (size_t)DD*DD,  base + 7*(size_t)DD*DD, nullptr, 0 };
            j[6] = { w_g + (size_t)h*4*DD*DD, base + 4*(size_t)DD*DD, base + 5*(size_t)DD*DD, 1 };
        }
        transpose_all<<<dim3(16,16,14), dim3(32,8)>>>(TA);
    }

    const dim3 ggrid(4, 32, 2);   // N tiles, M tiles, pair
    const __half* node = numencH;
    __half* nodeOutH[2] = { nodeH0, nodeH1 };

    for (int h = 0; h < HH; h++) {
        __half* base = WT + (size_t)h*8*DD*DD;

        // u1 = g_gt @ node, u2 = g_lt @ node (prefix/suffix form)
        graph_agg2<<<BB, 256>>>((const __half2*)node, (const __half2*)node,
                                (__half2*)t1h, (__half2*)t2h, perm, Vv);

        // v1 = relu(u1@w1a + b), v2 = relu(u2@w2a + b)
        {
            GemmPair P = {};
            P.A[0]=t1h; P.W[0]=base+0*(size_t)DD*DD; P.bias[0]=b_n1a+h*DD; P.outH[0]=t3h;
            P.A[1]=t2h; P.W[1]=base+2*(size_t)DD*DD; P.bias[1]=b_n2a+h*DD; P.outH[1]=t4h;
            gemm_mma<1><<<ggrid, 256, SMEM_DYN>>>(P);
        }

        // u1b = g_gt @ v1, u2b = g_lt @ v2
        graph_agg2<<<BB, 256>>>((const __half2*)t3h, (const __half2*)t4h,
                                (__half2*)t1h, (__half2*)t2h, perm, Vv);

        // ni1 = relu(u1b@w1b + b), ni2 = relu(u2b@w2b + b)
        {
            GemmPair P = {};
            P.A[0]=t1h; P.W[0]=base+1*(size_t)DD*DD; P.bias[0]=b_n1b+h*DD; P.outH[0]=ni1h;
            P.A[1]=t2h; P.W[1]=base+3*(size_t)DD*DD; P.bias[1]=b_n2b+h*DD; P.outH[1]=ni2h;
            gemm_mma<1><<<ggrid, 256, SMEM_DYN>>>(P);
        }

        // gate partials: p0 = ni1@Wg1, p1 = ni2@Wg2
        {
            GemmPair P = {};
            P.A[0]=ni1h; P.W[0]=base+4*(size_t)DD*DD; P.outF[0]=p0;
            P.A[1]=ni2h; P.W[1]=base+5*(size_t)DD*DD; P.outF[1]=p1;
            gemm_mma<0><<<ggrid, 256, SMEM_DYN>>>(P);
        }
        combine_gate<<<MM*DD/4/256, 256>>>((const float4*)p0, (const float4*)p1,
                                           (const float4*)(b_g + h*DD),
                                           (const __half2*)ni1h, (const __half2*)ni2h,
                                           (__half2*)ninfoh);

        // output partials: p0 = node@woA, p1 = ninfo@woB
        {
            GemmPair P = {};
            P.A[0]=node;   P.W[0]=base+6*(size_t)DD*DD; P.outF[0]=p0;
            P.A[1]=ninfoh; P.W[1]=base+7*(size_t)DD*DD; P.outF[1]=p1;
            gemm_mma<0><<<ggrid, 256, SMEM_DYN>>>(P);
        }
        combine_relu<<<MM*DD/4/256, 256>>>((const float4*)p0, (const float4*)p1,
                                           (const float4*)(b_o + h*DD),
                                           (__half2*)nodeOutH[h], (float4*)nodeF,
                                           (h == HH-1) ? (const float4*)numenc : nullptr,
                                           (float4*)out_ne);
        node = nodeOutH[h];
    }

    // assemble: gnn = enc + scatter(node); po = colmax (p1 reused as partial-max)
    fused_assemble<<<dim3(BB,4), 128>>>((const float4*)enc, (const float4*)nodeF,
                                        invmap, (float4*)out_gnn, (float4*)p1);
    reduce_po<<<64, 256>>>((const float4*)p1, (float4*)out_po);
}

// round 9
// speedup vs baseline: 1.8704x; 1.1073x over previous
#include <cuda_runtime.h>
#include <cuda_fp16.h>
#include <math.h>
#include <stdint.h>

#define BB 128
#define SS 512
#define NN 32
#define DD 512
#define HH 2
#define MM (BB*NN)   // 4096 rows

#define KCH 64                  // fp16 elements per pipeline chunk (128 B/row)
#define HPITCH 72               // smem row pitch in halves (144 B, conflict-free ldsm)
#define ABYTES (128*HPITCH*2)   // 18432 per matrix per stage
#define STGB (2*ABYTES)         // 36864 per stage (A+B)
#define NSTG 3
#define SMEM_DYN (NSTG*STGB)    // 110592 -> 2 CTAs/SM

// ---------------- scratch (device globals; no allocation) ----------------
__device__ int   invmap_buf[BB*SS];
__device__ int   perm_buf[BB*NN];
__device__ int   V_buf[BB];
__device__ float  buf_p0[MM*DD];          // fp32 split-K partials (+ po_part reuse)
__device__ float  buf_p1[MM*DD];
__device__ float  buf_nodeF[MM*DD];       // fp32 final node (for assembly)
__device__ __half buf_numencH[MM*DD];
__device__ __half buf_t1h[MM*DD];
__device__ __half buf_t2h[MM*DD];
__device__ __half buf_t3h[MM*DD];
__device__ __half buf_t4h[MM*DD];
__device__ __half buf_ni1h[MM*DD];
__device__ __half buf_ni2h[MM*DD];
__device__ __half buf_ninfoh[MM*DD];
__device__ __half buf_nodeH[2][MM*DD];
__device__ __half buf_WT[16*DD*DD];       // transposed fp16 weights [N,K]

// ---------------- helpers ----------------
__device__ __forceinline__ uint32_t smem_u32(const void* p) {
    return (uint32_t)__cvta_generic_to_shared(p);
}
__device__ __forceinline__ void cp_async16(uint32_t dst, const void* src) {
    asm volatile("cp.async.cg.shared.global [%0], [%1], 16;" :: "r"(dst), "l"(src));
}
__device__ __forceinline__ void mma_f16(float* c, const uint32_t* a,
                                        uint32_t b0, uint32_t b1) {
    asm volatile("mma.sync.aligned.m16n8k16.row.col.f32.f16.f16.f32 "
                 "{%0,%1,%2,%3}, {%4,%5,%6,%7}, {%8,%9}, {%0,%1,%2,%3};"
                 : "+f"(c[0]), "+f"(c[1]), "+f"(c[2]), "+f"(c[3])
                 : "r"(a[0]), "r"(a[1]), "r"(a[2]), "r"(a[3]), "r"(b0), "r"(b1));
}
__device__ __forceinline__ void ldsm_x4(uint32_t addr, uint32_t* r) {
    asm volatile("ldmatrix.sync.aligned.m8n8.x4.shared.b16 {%0,%1,%2,%3}, [%4];"
                 : "=r"(r[0]), "=r"(r[1]), "=r"(r[2]), "=r"(r[3]) : "r"(addr));
}

// ---------------- meta: invmap + rank permutation + valid count ----------------
__global__ void build_meta(const int* __restrict__ order, const int* __restrict__ pos,
                           int* __restrict__ invmap, int* __restrict__ perm,
                           int* __restrict__ Vv) {
    int b = blockIdx.x, tid = threadIdx.x;    // 512 threads
    __shared__ int ord[NN];
    if (tid < NN) ord[tid] = order[b*NN + tid];
    invmap[b*SS + tid] = -1;
    __syncthreads();
    if (tid < NN) {
        int p = pos[b*NN + tid];
        if (p >= 0) invmap[b*SS + p] = b*NN + tid;
        int o = ord[tid];
        bool valid = o > 0;
        int cntLess = 0, cntValid = 0, cntPadB = 0;
        #pragma unroll
        for (int m = 0; m < NN; m++) {
            int om = ord[m];
            bool vm = om > 0;
            cntValid += vm ? 1 : 0;
            cntLess  += (vm && om < o) ? 1 : 0;
            cntPadB  += (!vm && m < tid) ? 1 : 0;
        }
        int r = valid ? cntLess : (cntValid + cntPadB);
        perm[b*NN + r] = tid;
        if (tid == 0) Vv[b] = cntValid;
    }
}

// ---------------- fp32 -> fp16 convert ----------------
__global__ void f2h(const float2* __restrict__ src, __half2* __restrict__ dst, int n2) {
    int i = blockIdx.x*blockDim.x + threadIdx.x;
    int stride = gridDim.x*blockDim.x;
    for (; i < n2; i += stride) dst[i] = __float22half2_rn(src[i]);
}

// ---------------- dual graph aggregation via prefix/suffix sums ----------------
// z=0: y1 = g_gt @ x0 (prefix).  z=1: y2 = g_lt @ x1 (suffix).
// grid (BB, 2, 2), 128 threads; blockIdx.y selects the half2-column half.
__global__ void __launch_bounds__(128)
graph_agg2(const __half2* __restrict__ x0, const __half2* __restrict__ x1,
           __half2* __restrict__ y1, __half2* __restrict__ y2,
           const int* __restrict__ perm, const int* __restrict__ Vv) {
    int b = blockIdx.x;
    int t = blockIdx.y*128 + threadIdx.x;      // half2 column 0..255
    __shared__ int pm[NN];
    __shared__ int Vs;
    if (threadIdx.x < NN) pm[threadIdx.x] = perm[b*NN + threadIdx.x];
    if (threadIdx.x == 0) Vs = Vv[b];
    __syncthreads();
    const int V = Vs;
    const size_t base = (size_t)b*NN*256 + t;

    float2 xv[NN];
    float2 run = make_float2(0.f, 0.f);
    if (blockIdx.z == 0) {
        // gt prefix on x0 -> y1 (rank order)
        #pragma unroll
        for (int rr = 0; rr < NN; rr++)
            xv[rr] = __half22float2(x0[base + (size_t)pm[rr]*256]);
        #pragma unroll
        for (int rr = 0; rr < NN; rr++) {
            const float inv = 1.f/(float)(rr + 1);
            float2 o;
            if (rr < V) {
                o.x = (run.x + xv[rr].x) * inv;
                o.y = (run.y + xv[rr].y) * inv;
                run.x += xv[rr].x; run.y += xv[rr].y;
            } else {
                o = xv[rr];
            }
            y1[base + (size_t)pm[rr]*256] = __floats2half2_rn(o.x, o.y);
        }
    } else {
        // lt suffix on x1 -> y2 (reverse rank order)
        #pragma unroll
        for (int rr = 0; rr < NN; rr++) {
            int sr = (rr < V) ? (V - 1 - rr) : rr;
            xv[rr] = __half22float2(x1[base + (size_t)pm[sr]*256]);
        }
        #pragma unroll
        for (int rr = 0; rr < NN; rr++) {
            const float inv = 1.f/(float)(rr + 1);
            int sr = (rr < V) ? (V - 1 - rr) : rr;
            float2 o;
            if (rr < V) {
                o.x = (run.x + xv[rr].x) * inv;
                o.y = (run.y + xv[rr].y) * inv;
                run.x += xv[rr].x; run.y += xv[rr].y;
            } else {
                o = xv[rr];
            }
            y2[base + (size_t)pm[sr]*256] = __floats2half2_rn(o.x, o.y);
        }
    }
}

// ---------------- single-launch weight transpose ([K,N]->[N,K] fp16) -----------
struct TJob { const float* src; __half* d1; __half* d2; int gate; };
struct TArgs { TJob j[14]; };

__global__ void transpose_all(TArgs A) {
    TJob job = A.j[blockIdx.z];
    __shared__ float t1s[32][33], t2s[32][33];
    int k0 = blockIdx.x*32, n0 = blockIdx.y*32;
    int tx = threadIdx.x, ty = threadIdx.y;
    if (!job.gate) {
        #pragma unroll
        for (int i = 0; i < 4; i++)
            t1s[ty + i*8][tx] = job.src[(size_t)(k0 + ty + i*8)*DD + n0 + tx];
        __syncthreads();
        #pragma unroll
        for (int i = 0; i < 4; i++)
            job.d1[(size_t)(n0 + ty + i*8)*DD + k0 + tx] = __float2half(t1s[tx][ty + i*8]);
    } else {
        #pragma unroll
        for (int i = 0; i < 4; i++) {
            int k = k0 + ty + i*8, n = n0 + tx;
            float w0 = job.src[(size_t)k*DD + n];
            float w1 = job.src[(size_t)(DD + k)*DD + n];
            float w2 = job.src[(size_t)(2*DD + k)*DD + n];
            float w3 = job.src[(size_t)(3*DD + k)*DD + n];
            t1s[ty + i*8][tx] = w0 + w2 + w3;
            t2s[ty + i*8][tx] = w1 + w2 - w3;
        }
        __syncthreads();
        #pragma unroll
        for (int i = 0; i < 4; i++) {
            size_t o = (size_t)(n0 + ty + i*8)*DD + k0 + tx;
            job.d1[o] = __float2half(t1s[tx][ty + i*8]);
            job.d2[o] = __float2half(t2s[tx][ty + i*8]);
        }
    }
}

// ---------------- FP16 mma.sync GEMM ----------------
// out_z = epi(A_z @ W_z^T [+ bias_z]); EPI 0: raw fp32 partials, EPI 1: bias+relu fp16
struct GemmPair {
    const __half *A[2], *W[2];
    const float *bias[2];
    float  *outF[2];
    __half *outH[2];
};

__device__ __forceinline__ void load_chunk(uint32_t smbase, const __half* Asrc,
                                           const __half* Wsrc, int bm, int bn,
                                           int kk, int tid) {
    #pragma unroll
    for (int j = 0; j < 4; j++) {
        int f = tid + 256*j; int row = f >> 3, c = f & 7;
        cp_async16(smbase + row*(HPITCH*2) + c*16,
                   Asrc + (size_t)(bm + row)*512 + kk + c*8);
    }
    #pragma unroll
    for (int j = 0; j < 4; j++) {
        int f = tid + 256*j; int row = f >> 3, c = f & 7;
        cp_async16(smbase + ABYTES + row*(HPITCH*2) + c*16,
                   Wsrc + (size_t)(bn + row)*512 + kk + c*8);
    }
}

template<int EPI>
__global__ void __launch_bounds__(256, 2)
gemm_mma(GemmPair P)
{
    const int z = blockIdx.z;
    const __half* A = P.A[z]; const __half* W = P.W[z];
    const float* bias = P.bias[z];
    float*  outF = P.outF[z];
    __half* outH = P.outH[z];

    extern __shared__ char sm[];
    const int bm = blockIdx.y * 128, bn = blockIdx.x * 128;
    const int tid = threadIdx.x, wid = tid >> 5, lane = tid & 31;
    const int wm = (wid >> 1) * 32, wn = (wid & 1) * 64;

    // ldmatrix lane addressing (bytes); quadrant col offset = 16 B (8 halves)
    const int laneAr = (lane & 7) + ((lane & 8) ? 8 : 0);
    const int laneAc = (lane & 16) ? 8 : 0;
    const int laneBr = (lane & 7) + ((lane & 16) ? 8 : 0);
    const int laneBc = (lane & 8) ? 8 : 0;
    const uint32_t smb = smem_u32(sm);
    uint32_t aAddr[2], bAddr[4];
    #pragma unroll
    for (int mi = 0; mi < 2; mi++)
        aAddr[mi] = smb + ((wm + mi*16 + laneAr)*HPITCH + laneAc)*2;
    #pragma unroll
    for (int p = 0; p < 4; p++)
        bAddr[p] = smb + ABYTES + ((wn + p*16 + laneBr)*HPITCH + laneBc)*2;

    float acc[2][8][4];
    #pragma unroll
    for (int i = 0; i < 2; i++)
        #pragma unroll
        for (int j = 0; j < 8; j++)
            #pragma unroll
            for (int q = 0; q < 4; q++) acc[i][j][q] = 0.f;

    const int NC = 512 / KCH;   // 8

    // prologue: chunks 0,1 -> stages 0,1
    load_chunk(smb, A, W, bm, bn, 0, tid);
    asm volatile("cp.async.commit_group;");
    load_chunk(smb + STGB, A, W, bm, bn, KCH, tid);
    asm volatile("cp.async.commit_group;");

    int rs = 0, ws = 2;
    #pragma unroll 1
    for (int kc = 0; kc < NC; kc++) {
        if (kc + 1 < NC) asm volatile("cp.async.wait_group 1;");
        else             asm volatile("cp.async.wait_group 0;");
        __syncthreads();

        if (kc + 2 < NC) {
            load_chunk(smb + ws*STGB, A, W, bm, bn, (kc + 2)*KCH, tid);
            asm volatile("cp.async.commit_group;");
        }

        const uint32_t soff = (uint32_t)rs * STGB;
        #pragma unroll
        for (int s4 = 0; s4 < 4; s4++) {           // 4 x k16
            const uint32_t koff = soff + s4*32;    // 16 halves = 32 B
            uint32_t aF[2][4], bF[4][4];
            ldsm_x4(aAddr[0] + koff, aF[0]);
            ldsm_x4(aAddr[1] + koff, aF[1]);
            #pragma unroll
            for (int p = 0; p < 4; p++) ldsm_x4(bAddr[p] + koff, bF[p]);
            #pragma unroll
            for (int p = 0; p < 4; p++) {
                mma_f16(acc[0][2*p],   aF[0], bF[p][0], bF[p][1]);
                mma_f16(acc[1][2*p],   aF[1], bF[p][0], bF[p][1]);
                mma_f16(acc[0][2*p+1], aF[0], bF[p][2], bF[p][3]);
                mma_f16(acc[1][2*p+1], aF[1], bF[p][2], bF[p][3]);
            }
        }
        rs = (rs + 1 == NSTG) ? 0 : rs + 1;
        ws = (ws + 1 == NSTG) ? 0 : ws + 1;
    }

    // epilogue
    const int r0 = bm + wm + (lane >> 2);
    const int cbase = bn + wn + (lane & 3)*2;
    float bb0[8], bb1[8];
    if (EPI == 1) {
        #pragma unroll
        for (int ni = 0; ni < 8; ni++) {
            bb0[ni] = bias[cbase + ni*8];
            bb1[ni] = bias[cbase + ni*8 + 1];
        }
    }
    #pragma unroll
    for (int mi = 0; mi < 2; mi++) {
        int row0 = r0 + mi*16, row1 = row0 + 8;
        #pragma unroll
        for (int ni = 0; ni < 8; ni++) {
            int col = cbase + ni*8;
            float v0 = acc[mi][ni][0], v1 = acc[mi][ni][1];
            float v2 = acc[mi][ni][2], v3 = acc[mi][ni][3];
            if (EPI == 1) {
                v0 = fmaxf(v0 + bb0[ni], 0.f); v1 = fmaxf(v1 + bb1[ni], 0.f);
                v2 = fmaxf(v2 + bb0[ni], 0.f); v3 = fmaxf(v3 + bb1[ni], 0.f);
                *(__half2*)(outH + (size_t)row0*512 + col) = __floats2half2_rn(v0, v1);
                *(__half2*)(outH + (size_t)row1*512 + col) = __floats2half2_rn(v2, v3);
            } else {
                *(float2*)(outF + (size_t)row0*512 + col) = make_float2(v0, v1);
                *(float2*)(outF + (size_t)row1*512 + col) = make_float2(v2, v3);
            }
        }
    }
}

// ---------------- split-K combine kernels ----------------
__global__ void combine_gate(const float4* __restrict__ p0, const float4* __restrict__ p1,
                             const float4* __restrict__ bias,
                             const __half2* __restrict__ e1, const __half2* __restrict__ e2,
                             __half2* __restrict__ out) {
    int i = blockIdx.x*256 + threadIdx.x;       // MM*DD/4
    float4 a = p0[i], b = p1[i], bi = bias[i & 127];
    float2 x0 = __half22float2(e1[2*i]),   x1 = __half22float2(e1[2*i+1]);
    float2 y0 = __half22float2(e2[2*i]),   y1 = __half22float2(e2[2*i+1]);
    float g0 = 1.f/(1.f + expf(-(a.x + b.x + bi.x)));
    float g1 = 1.f/(1.f + expf(-(a.y + b.y + bi.y)));
    float g2 = 1.f/(1.f + expf(-(a.z + b.z + bi.z)));
    float g3 = 1.f/(1.f + expf(-(a.w + b.w + bi.w)));
    out[2*i]   = __floats2half2_rn(g0*x0.x + (1.f-g0)*y0.x, g1*x0.y + (1.f-g1)*y0.y);
    out[2*i+1] = __floats2half2_rn(g2*x1.x + (1.f-g2)*y1.x, g3*x1.y + (1.f-g3)*y1.y);
}

__global__ void combine_relu(const float4* __restrict__ p0, const float4* __restrict__ p1,
                             const float4* __restrict__ bias,
                             __half2* __restrict__ outH, float4* __restrict__ outF,
                             const float4* __restrict__ addsrc, float4* __restrict__ out2) {
    int i = blockIdx.x*256 + threadIdx.x;
    float4 a = p0[i], b = p1[i], bi = bias[i & 127];
    float4 v = make_float4(fmaxf(a.x + b.x + bi.x, 0.f), fmaxf(a.y + b.y + bi.y, 0.f),
                           fmaxf(a.z + b.z + bi.z, 0.f), fmaxf(a.w + b.w + bi.w, 0.f));
    outH[2*i]   = __floats2half2_rn(v.x, v.y);
    outH[2*i+1] = __floats2half2_rn(v.z, v.w);
    outF[i] = v;
    if (addsrc) {
        float4 s = addsrc[i];
        out2[i] = make_float4(s.x + v.x, s.y + v.y, s.z + v.z, s.w + v.w);
    }
}

// ---------------- output assembly (float4, s split 8-ways + partial max) -------
__global__ void fused_assemble(const float4* __restrict__ enc,
                               const float4* __restrict__ node,
                               const int* __restrict__ invmap,
                               float4* __restrict__ gnn, float4* __restrict__ po_part) {
    int b = blockIdx.x, q = blockIdx.y, t = threadIdx.x;   // 128 threads, q in 0..7
    __shared__ int inv[64];
    if (t < 64) inv[t] = invmap[b*SS + q*64 + t];
    __syncthreads();
    float4 m = make_float4(-3.402823466e38f, -3.402823466e38f,
                           -3.402823466e38f, -3.402823466e38f);
    #pragma unroll 4
    for (int si = 0; si < 64; si++) {
        int s = q*64 + si;
        size_t o = ((size_t)s*BB + b)*128 + t;
        float4 v = enc[o];
        int iv = inv[si];
        if (iv >= 0) {
            float4 nv = node[(size_t)iv*128 + t];
            v.x += nv.x; v.y += nv.y; v.z += nv.z; v.w += nv.w;
        }
        gnn[o] = v;
        m.x = fmaxf(m.x, v.x); m.y = fmaxf(m.y, v.y);
        m.z = fmaxf(m.z, v.z); m.w = fmaxf(m.w, v.w);
    }
    po_part[((size_t)q*BB + b)*128 + t] = m;
}

__global__ void reduce_po(const float4* __restrict__ pp, float4* __restrict__ po) {
    int i = blockIdx.x*256 + threadIdx.x;      // BB*DD/4 = 16384
    float4 m = pp[i];
    #pragma unroll
    for (int q = 1; q < 8; q++) {
        float4 v = pp[i + q*16384];
        m.x = fmaxf(m.x, v.x); m.y = fmaxf(m.y, v.y);
        m.z = fmaxf(m.z, v.z); m.w = fmaxf(m.w, v.w);
    }
    po[i] = m;
}

// ---------------- host launch ----------------
extern "C" void kernel_launch(void* const* d_in, const int* in_sizes, int n_in,
                              void* d_out, int out_size) {
    const float* enc    = (const float*)d_in[0];   // [S,B,D]
    const float* numenc = (const float*)d_in[1];   // [B,N,D]
    const int*   pos    = (const int*)d_in[2];     // [B,N]
    const int*   order  = (const int*)d_in[3];     // [B,N]
    const float* w_n1a  = (const float*)d_in[4];
    const float* b_n1a  = (const float*)d_in[5];
    const float* w_n1b  = (const float*)d_in[6];
    const float* b_n1b  = (const float*)d_in[7];
    const float* w_n2a  = (const float*)d_in[8];
    const float* b_n2a  = (const float*)d_in[9];
    const float* w_n2b  = (const float*)d_in[10];
    const float* b_n2b  = (const float*)d_in[11];
    const float* w_g    = (const float*)d_in[12];  // [H,4D,D]
    const float* b_g    = (const float*)d_in[13];
    const float* w_o    = (const float*)d_in[14];  // [H,2D,D]
    const float* b_o    = (const float*)d_in[15];

    float* out     = (float*)d_out;
    float* out_gnn = out;                                    // [S,B,D]
    float* out_ne  = out + (size_t)SS*BB*DD;                 // [B,N,D]
    float* out_po  = out_ne + (size_t)BB*NN*DD;              // [B,D]

    float *p0, *p1, *nodeF;
    __half *numencH, *t1h, *t2h, *t3h, *t4h, *ni1h, *ni2h, *ninfoh, *nodeH0, *nodeH1, *WT;
    int *invmap, *perm, *Vv;
    cudaGetSymbolAddress((void**)&invmap,  invmap_buf);
    cudaGetSymbolAddress((void**)&perm,    perm_buf);
    cudaGetSymbolAddress((void**)&Vv,      V_buf);
    cudaGetSymbolAddress((void**)&p0,      buf_p0);
    cudaGetSymbolAddress((void**)&p1,      buf_p1);
    cudaGetSymbolAddress((void**)&nodeF,   buf_nodeF);
    cudaGetSymbolAddress((void**)&numencH, buf_numencH);
    cudaGetSymbolAddress((void**)&t1h,     buf_t1h);
    cudaGetSymbolAddress((void**)&t2h,     buf_t2h);
    cudaGetSymbolAddress((void**)&t3h,     buf_t3h);
    cudaGetSymbolAddress((void**)&t4h,     buf_t4h);
    cudaGetSymbolAddress((void**)&ni1h,    buf_ni1h);
    cudaGetSymbolAddress((void**)&ni2h,    buf_ni2h);
    cudaGetSymbolAddress((void**)&ninfoh,  buf_ninfoh);
    cudaGetSymbolAddress((void**)&nodeH0,  buf_nodeH);
    nodeH1 = nodeH0 + (size_t)MM*DD;
    cudaGetSymbolAddress((void**)&WT,      buf_WT);

    cudaFuncSetAttribute(gemm_mma<0>, cudaFuncAttributeMaxDynamicSharedMemorySize, SMEM_DYN);
    cudaFuncSetAttribute(gemm_mma<1>, cudaFuncAttributeMaxDynamicSharedMemorySize, SMEM_DYN);

    build_meta<<<BB, SS>>>(order, pos, invmap, perm, Vv);
    f2h<<<512, 256>>>((const float2*)numenc, (__half2*)numencH, MM*DD/2);

    // all weight transposes in one launch (fp16 [N,K])
    {
        TArgs TA;
        for (int h = 0; h < HH; h++) {
            __half* base = WT + (size_t)h*8*DD*DD;
            TJob* j = TA.j + h*7;
            j[0] = { w_n1a + (size_t)h*DD*DD, base + 0*(size_t)DD*DD, nullptr, 0 };
            j[1] = { w_n1b + (size_t)h*DD*DD, base + 1*(size_t)DD*DD, nullptr, 0 };
            j[2] = { w_n2a + (size_t)h*DD*DD, base + 2*(size_t)DD*DD, nullptr, 0 };
            j[3] = { w_n2b + (size_t)h*DD*DD, base + 3*(size_t)DD*DD, nullptr, 0 };
            j[4] = { w_o + (size_t)h*2*DD*DD,                  base + 6*(size_t)DD*DD, nullptr, 0 };
            j[5] = { w_o + (size_t)h*2*DD*DD + (size_t)DD*DD,  base + 7*(size_t)DD*DD, nullptr, 0 };
            j[6] = { w_g + (size_t)h*4*DD*DD, base + 4*(size_t)DD*DD, base + 5*(size_t)DD*DD, 1 };
        }
        transpose_all<<<dim3(16,16,14), dim3(32,8)>>>(TA);
    }

    const dim3 ggrid(4, 32, 2);   // N tiles, M tiles, pair
    const dim3 agrid(BB, 2, 2);   // batch, col-half, phase
    const __half* node = numencH;
    __half* nodeOutH[2] = { nodeH0, nodeH1 };

    for (int h = 0; h < HH; h++) {
        __half* base = WT + (size_t)h*8*DD*DD;

        // u1 = g_gt @ node, u2 = g_lt @ node (prefix/suffix form)
        graph_agg2<<<agrid, 128>>>((const __half2*)node, (const __half2*)node,
                                   (__half2*)t1h, (__half2*)t2h, perm, Vv);

        // v1 = relu(u1@w1a + b), v2 = relu(u2@w2a + b)
        {
            GemmPair P = {};
            P.A[0]=t1h; P.W[0]=base+0*(size_t)DD*DD; P.bias[0]=b_n1a+h*DD; P.outH[0]=t3h;
            P.A[1]=t2h; P.W[1]=base+2*(size_t)DD*DD; P.bias[1]=b_n2a+h*DD; P.outH[1]=t4h;
            gemm_mma<1><<<ggrid, 256, SMEM_DYN>>>(P);
        }

        // u1b = g_gt @ v1, u2b = g_lt @ v2
        graph_agg2<<<agrid, 128>>>((const __half2*)t3h, (const __half2*)t4h,
                                   (__half2*)t1h, (__half2*)t2h, perm, Vv);

        // ni1 = relu(u1b@w1b + b), ni2 = relu(u2b@w2b + b)
        {
            GemmPair P = {};
            P.A[0]=t1h; P.W[0]=base+1*(size_t)DD*DD; P.bias[0]=b_n1b+h*DD; P.outH[0]=ni1h;
            P.A[1]=t2h; P.W[1]=base+3*(size_t)DD*DD; P.bias[1]=b_n2b+h*DD; P.outH[1]=ni2h;
            gemm_mma<1><<<ggrid, 256, SMEM_DYN>>>(P);
        }

        // gate partials: p0 = ni1@Wg1, p1 = ni2@Wg2
        {
            GemmPair P = {};
            P.A[0]=ni1h; P.W[0]=base+4*(size_t)DD*DD; P.outF[0]=p0;
            P.A[1]=ni2h; P.W[1]=base+5*(size_t)DD*DD; P.outF[1]=p1;
            gemm_mma<0><<<ggrid, 256, SMEM_DYN>>>(P);
        }
        combine_gate<<<MM*DD/4/256, 256>>>((const float4*)p0, (const float4*)p1,
                                           (const float4*)(b_g + h*DD),
                                           (const __half2*)ni1h, (const __half2*)ni2h,
                                           (__half2*)ninfoh);

        // output partials: p0 = node@woA, p1 = ninfo@woB
        {
            GemmPair P = {};
            P.A[0]=node;   P.W[0]=base+6*(size_t)DD*DD; P.outF[0]=p0;
            P.A[1]=ninfoh; P.W[1]=base+7*(size_t)DD*DD; P.outF[1]=p1;
            gemm_mma<0><<<ggrid, 256, SMEM_DYN>>>(P);
        }
        combine_relu<<<MM*DD/4/256, 256>>>((const float4*)p0, (const float4*)p1,
                                           (const float4*)(b_o + h*DD),
                                           (__half2*)nodeOutH[h], (float4*)nodeF,
                                           (h == HH-1) ? (const float4*)numenc : nullptr,
                                           (float4*)out_ne);
        node = nodeOutH[h];
    }

    // assemble: gnn = enc + scatter(node); po = colmax (p1 reused as partial-max)
    fused_assemble<<<dim3(BB,8), 128>>>((const float4*)enc, (const float4*)nodeF,
                                        invmap, (float4*)out_gnn, (float4*)p1);
    reduce_po<<<64, 256>>>((const float4*)p1, (float4*)out_po);
}